// round 14
// baseline (speedup 1.0000x reference)
#include <cuda_runtime.h>
#include <cuda_bf16.h>
#include <cstdint>

// ---------------------------------------------------------------------------
// SimplePose via tcgen05 bf16 hi/lo 3-pass GEMMs (fp32-near precision).
//   3x (conv_transpose k4 s2 pads(1,1) + BN + ReLU) -> 1x1 conv -> argmax det
// Phase decomposition (py,px): kh = 2a+1-py, iy = ty+a  -> dense GEMM
//   M = B*(H-1)*(W-1), K = 4*Cin, N = 256 per phase.
// Emulation: v = hi + lo with hi = bf16(v), lo = bf16(v - hi).
//   C = Ah*Bh + Ah*Bl + Al*Bh  (3 bf16 tcgen05 passes, fp32 TMEM accum)
//
// Round 14: TS-mode MMA — A lives in TMEM (LDG -> regs -> tcgen05.st, off
// the SMEM port), only B flows through SMEM. Measured bottleneck was the
// SMEM port (L1TEX 81.6% vs tensor 36.4%); port traffic/chunk drops
// 320KB -> 128KB, making tensor the binding pipe. Tiles M=128 x N=256
// (TMEM: D 256 cols + 3 ring A slots x 32 cols = 352 <= 512).
// ---------------------------------------------------------------------------

#if defined(__CUDA_ARCH_FEAT_SM103_ALL) || defined(__CUDA_ARCH_FEAT_SM100_ALL)
#define TCPATH 1
#else
#define TCPATH 0
#endif

#define BDIM_B   64
#define COUT     256
#define KPT      17
#define BN_EPS   1e-5f
#define HD 50
#define WD 34
#define HWD (HD * WD)          // 1700
#define NTHR 288               // warps 0-3: A->TMEM, 4-7: B->SMEM, 8: MMA

#define L1_MPAD 2304
#define L1_M 2240              // 64 * 7 * 5

typedef __nv_bfloat16 bf16;

// ---------------- scratch (static; cudaMalloc forbidden) -------------------
__device__ bf16  g_xh[BDIM_B * 8 * 6 * 2048];
__device__ bf16  g_xl[BDIM_B * 8 * 6 * 2048];
__device__ bf16  g_w1h[16 * COUT * 2048];
__device__ bf16  g_w1l[16 * COUT * 2048];
__device__ bf16  g_w2h[16 * COUT * 256];
__device__ bf16  g_w2l[16 * COUT * 256];
__device__ bf16  g_w3h[16 * COUT * 256];
__device__ bf16  g_w3l[16 * COUT * 256];
__device__ float g_p1 [4 * 4 * L1_MPAD * COUT];
__device__ bf16  g_y1h[BDIM_B * 14 * 10 * COUT];
__device__ bf16  g_y1l[BDIM_B * 14 * 10 * COUT];
__device__ bf16  g_y2h[BDIM_B * 26 * 18 * COUT];
__device__ bf16  g_y2l[BDIM_B * 26 * 18 * COUT];
__device__ float g_hm [BDIM_B * KPT * HWD];

// ---------------------------- helpers --------------------------------------
__device__ __forceinline__ void split_bf(float v, bf16& h, bf16& l) {
    h = __float2bfloat16_rn(v);
    l = __float2bfloat16_rn(v - __bfloat162float(h));
}

#if TCPATH
__device__ __forceinline__ uint32_t smem_u32(const void* p) {
    uint32_t a;
    asm("{ .reg .u64 t; cvta.to.shared.u64 t, %1; cvt.u32.u64 %0, t; }" : "=r"(a) : "l"(p));
    return a;
}
__device__ __forceinline__ uint32_t elect_one() {
    uint32_t pr;
    asm volatile("{\n\t.reg .pred p;\n\telect.sync _|p, 0xFFFFFFFF;\n\tselp.b32 %0, 1, 0, p;\n\t}" : "=r"(pr));
    return pr;
}

#define MBARRIER_INIT(addr, cnt) \
    asm volatile("mbarrier.init.shared.b64 [%0], %1;" :: "r"(addr), "r"(cnt) : "memory")
#define MBARRIER_INVAL(addr) \
    asm volatile("mbarrier.inval.shared.b64 [%0];" :: "r"(addr) : "memory")
#define MBARRIER_ARRIVE(addr) \
    asm volatile("mbarrier.arrive.release.cta.shared::cta.b64 _, [%0];" :: "r"(addr) : "memory")
__device__ __forceinline__ void mbar_wait(uint32_t mbar, uint32_t parity) {
    asm volatile(
        "{\n\t.reg .pred P;\n\t"
        "WL%=:\n\t"
        "mbarrier.try_wait.parity.acquire.cta.shared::cta.b64 P, [%0], %1, 0x989680;\n\t"
        "@P bra.uni WD%=;\n\t"
        "bra.uni WL%=;\n\t"
        "WD%=:\n\t}"
        :: "r"(mbar), "r"(parity) : "memory");
}
#define TCGEN05_ALLOC(sm, n) \
    asm volatile("tcgen05.alloc.cta_group::1.sync.aligned.shared::cta.b32 [%0], %1;" :: "r"(sm), "r"(n) : "memory")
#define TCGEN05_DEALLOC(tm, n) \
    asm volatile("tcgen05.dealloc.cta_group::1.sync.aligned.b32 %0, %1;" :: "r"(tm), "r"(n))
#define TCGEN05_RELINQ() \
    asm volatile("tcgen05.relinquish_alloc_permit.cta_group::1.sync.aligned;")
#define TCGEN05_COMMIT(mb) \
    asm volatile("tcgen05.commit.cta_group::1.mbarrier::arrive::one.shared::cluster.b64 [%0];" :: "r"(mb) : "memory")
#define TCGEN05_FENCE_BEFORE() \
    asm volatile("tcgen05.fence::before_thread_sync;" ::: "memory")
#define TCGEN05_FENCE_AFTER() \
    asm volatile("tcgen05.fence::after_thread_sync;" ::: "memory")
#define TCGEN05_WAIT_LD() \
    asm volatile("tcgen05.wait::ld.sync.aligned;" ::: "memory")
#define TCGEN05_WAIT_ST() \
    asm volatile("tcgen05.wait::st.sync.aligned;" ::: "memory")
#define FENCE_ASYNC_SHARED() \
    asm volatile("fence.proxy.async.shared::cta;" ::: "memory")

#define TCGEN05_LD_X32(r, tm) \
    asm volatile( \
        "tcgen05.ld.sync.aligned.32x32b.x32.b32 " \
        "{%0, %1, %2, %3, %4, %5, %6, %7, " \
        " %8, %9, %10, %11, %12, %13, %14, %15, " \
        " %16, %17, %18, %19, %20, %21, %22, %23, " \
        " %24, %25, %26, %27, %28, %29, %30, %31}, [%32];" \
        : "=r"((r)[0]),  "=r"((r)[1]),  "=r"((r)[2]),  "=r"((r)[3]), \
          "=r"((r)[4]),  "=r"((r)[5]),  "=r"((r)[6]),  "=r"((r)[7]), \
          "=r"((r)[8]),  "=r"((r)[9]),  "=r"((r)[10]), "=r"((r)[11]), \
          "=r"((r)[12]), "=r"((r)[13]), "=r"((r)[14]), "=r"((r)[15]), \
          "=r"((r)[16]), "=r"((r)[17]), "=r"((r)[18]), "=r"((r)[19]), \
          "=r"((r)[20]), "=r"((r)[21]), "=r"((r)[22]), "=r"((r)[23]), \
          "=r"((r)[24]), "=r"((r)[25]), "=r"((r)[26]), "=r"((r)[27]), \
          "=r"((r)[28]), "=r"((r)[29]), "=r"((r)[30]), "=r"((r)[31]) \
        : "r"(tm))

#define TCGEN05_ST_X32(tm, r) \
    asm volatile( \
        "tcgen05.st.sync.aligned.32x32b.x32.b32 [%0], " \
        "{%1, %2, %3, %4, %5, %6, %7, %8, " \
        " %9, %10, %11, %12, %13, %14, %15, %16, " \
        " %17, %18, %19, %20, %21, %22, %23, %24, " \
        " %25, %26, %27, %28, %29, %30, %31, %32};" \
        :: "r"(tm), \
           "r"((r)[0]),  "r"((r)[1]),  "r"((r)[2]),  "r"((r)[3]), \
           "r"((r)[4]),  "r"((r)[5]),  "r"((r)[6]),  "r"((r)[7]), \
           "r"((r)[8]),  "r"((r)[9]),  "r"((r)[10]), "r"((r)[11]), \
           "r"((r)[12]), "r"((r)[13]), "r"((r)[14]), "r"((r)[15]), \
           "r"((r)[16]), "r"((r)[17]), "r"((r)[18]), "r"((r)[19]), \
           "r"((r)[20]), "r"((r)[21]), "r"((r)[22]), "r"((r)[23]), \
           "r"((r)[24]), "r"((r)[25]), "r"((r)[26]), "r"((r)[27]), \
           "r"((r)[28]), "r"((r)[29]), "r"((r)[30]), "r"((r)[31]) \
        : "memory")

// SMEM descriptor (K-major SW128: LBO=1, SBO=64, version=1, layout=2)
#define SMEM_DESC_BASE \
    ((uint64_t(2) << 61) | (uint64_t(1) << 46) | (uint64_t(64) << 32) | (uint64_t(1) << 16))
#define MAKE_DESC(addr) (SMEM_DESC_BASE | ((uint64_t)((addr) >> 4) & 0x3FFF))

// bf16 MMA, cta_group::1, M=128, N=256, K=16 per issue (TS: A in TMEM)
#define IDESC_BF16 ((1u << 4) | (1u << 7) | (1u << 10) | (32u << 17) | (8u << 24))

__device__ __forceinline__ void mma_bf16_ts(uint32_t d, uint32_t a_tm, uint64_t db,
                                            uint32_t en) {
    asm volatile(
        "{\n\t.reg .pred p;\n\t"
        "setp.ne.u32 p, %4, 0;\n\t"
        "tcgen05.mma.cta_group::1.kind::f16 [%0], [%1], %2, %3, {%5, %5, %5, %5}, p;\n\t"
        "}"
        :: "r"(d), "r"(a_tm), "l"(db), "r"(IDESC_BF16), "r"(en), "r"(0u)
        : "memory");
}
#endif  // TCPATH

#define SWZ(o) ((o) ^ (((o) >> 3) & 0x70))

// SMEM layout: B-only slots (256 rows x 128B = 32KB), ring of 3.
#define SLOT_BYTES 32768
#define SM_TMEMPTR 0
#define SM_FULL 8
#define SM_DONE 32
#define SM_SC 64
#define SM_BI (64 + 1024)
#define SL_STAGE0 4096
#define SM_WF (SL_STAGE0 + 3 * SLOT_BYTES)          // 102400
#define SMEM2_TOTAL (SM_WF + COUT * KPT * 4)         // 119808

// TMEM columns: D at 0..255; A ring slots at 256 + s3*32.
#define TM_D 0
#define TM_A 256

// ---------------------------------------------------------------------------
// Preprocess
// ---------------------------------------------------------------------------
__global__ void split_kernel(const float* __restrict__ in, bf16* __restrict__ hi,
                             bf16* __restrict__ lo, int n)
{
    for (int i = blockIdx.x * blockDim.x + threadIdx.x; i < n; i += gridDim.x * blockDim.x) {
        bf16 h, l; split_bf(in[i], h, l);
        hi[i] = h; lo[i] = l;
    }
}

__global__ void wtrans_kernel(const float* __restrict__ w, bf16* __restrict__ th,
                              bf16* __restrict__ tl, int Cin)
{
    __shared__ float tile[32][33];
    const int t = blockIdx.z;
    const int ci0 = blockIdx.x * 32, co0 = blockIdx.y * 32;
    const int tx = threadIdx.x, ty = threadIdx.y;
#pragma unroll
    for (int i = 0; i < 4; ++i)
        tile[ty + 8 * i][tx] = w[((size_t)(t * Cin + ci0 + ty + 8 * i)) * COUT + co0 + tx];
    __syncthreads();
#pragma unroll
    for (int i = 0; i < 4; ++i) {
        bf16 h, l; split_bf(tile[tx][ty + 8 * i], h, l);
        const size_t o = ((size_t)(t * COUT + co0 + ty + 8 * i)) * Cin + ci0 + tx;
        th[o] = h; tl[o] = l;
    }
}

#if TCPATH
// ---------------------------------------------------------------------------
// Shared TS-mode GEMM core (device inline): M=128 x N=256 tile, K via slots.
//   Warps 0-3: A rows -> TMEM (tcgen05.st).  Warps 4-7: B rows -> SMEM.
//   Warp 8: MMA issuer. full[s]: 256 arrivals. done[s]: commit. Ring 3, lag-3.
// ---------------------------------------------------------------------------
struct GemmCtx {
    uint32_t sb, tmem;
    const bf16 *Ah, *Al, *Wh, *Wl;
    size_t arow;        // base global offset of this thread's A row (A threads)
    int m0, M, Cin, NK; // NK = chunks of K64
};

__device__ __forceinline__ void gemm_ts_run(char* smem, const GemmCtx& c,
                                            int py, int px, int fixed_tap)
{
    const int tid = threadIdx.x;
    const int wid = tid >> 5;
    const uint32_t sb = c.sb;
    const int NSLOT = 2 * c.NK;

    if (wid < 4) {
        // ---------------- A loader: thread = one M row ---------------------
        for (int sl = 0; sl < NSLOT; ++sl) {
            const int s3 = sl % 3;
            if (sl >= 3) mbar_wait(sb + SM_DONE + s3 * 8, (uint32_t)(((sl / 3) - 1) & 1));
            const int chunk = sl >> 1, half = sl & 1;
            const int kt = chunk * 64;
            const int tap = (fixed_tap >= 0) ? fixed_tap : (kt / c.Cin);
            const int ci0 = (fixed_tap >= 0) ? kt : (kt - tap * c.Cin);
            const int a = tap >> 1, bt = tap & 1;
            const size_t aoff = (fixed_tap >= 0) ? (size_t)ci0
                                                 : ((size_t)(a * 0) + 0) + 0;  // patched below
            const bf16* pa = (half ? c.Al : c.Ah) + c.arow
                           + ((fixed_tap >= 0) ? (size_t)ci0
                                               : ((size_t)((a)) * 0)) ;
            (void)aoff;
            // For the generic (fixed_tap<0) case the caller pre-adds nothing;
            // compute full offset here:
            if (fixed_tap < 0) {
                // re-derive: arow points at (bb,ty,tx,0); add (a*W+bt)*Cin+ci0
                // W is encoded by caller into arow? No -- handled by caller via
                // passing W through c.m0? Simplify: caller passes W in c.NK? no.
                ;
            }
            uint32_t regs[32];
#pragma unroll
            for (int j = 0; j < 8; ++j) {
                const uint4 v = *(const uint4*)(pa + 8 * j);
                regs[4 * j + 0] = v.x; regs[4 * j + 1] = v.y;
                regs[4 * j + 2] = v.z; regs[4 * j + 3] = v.w;
            }
            TCGEN05_ST_X32(c.tmem + TM_A + s3 * 32 + ((uint32_t)wid << 21), regs);
            TCGEN05_WAIT_ST();
            TCGEN05_FENCE_BEFORE();
            MBARRIER_ARRIVE(sb + SM_FULL + s3 * 8);
        }
    }
}
#endif

// NOTE: the helper above proved awkward for the two distinct index schemes;
// the kernels below inline their loops directly instead (helper unused).

// ===========================================================================
// Kernel L1S: split-K-by-tap, M=128 x N=256 TS tiles for L1 (Cin=2048).
// grid (18 m-tiles, 4 phases, 4 taps). NK = 32, NSLOT = 64.
// ===========================================================================
__global__ __launch_bounds__(NTHR, 1)
void deconv_tc1s(const bf16* __restrict__ Ah, const bf16* __restrict__ Al,
                 const bf16* __restrict__ Wh, const bf16* __restrict__ Wl,
                 float* __restrict__ part)
{
    const int H = 8, W = 6, Cin = 2048;
    const int Hp = 7, Wp = 5, HWp = 35;
    const int M = L1_M;
#if TCPATH
    extern __shared__ char smem[];
    const uint32_t sb = smem_u32(smem);
    const int tid = threadIdx.x;
    const int wid = tid >> 5, lane = tid & 31;

    const int phase = blockIdx.y;
    const int tap = blockIdx.z;
    const int a = tap >> 1, bt = tap & 1;
    const int py = phase >> 1, px = phase & 1;
    const int kh = 2 * a + 1 - py, kw = 2 * bt + 1 - px;
    const int m0 = blockIdx.x * 128;
    const int NK = Cin >> 6;               // 32 chunks of K=64
    const int NSLOT = 2 * NK;              // 64 slots

    if (wid == 0) { TCGEN05_ALLOC(sb + SM_TMEMPTR, 512); TCGEN05_RELINQ(); }
    if (tid < 3) MBARRIER_INIT(sb + SM_FULL + tid * 8, 256);
    else if (tid >= 32 && tid < 35) MBARRIER_INIT(sb + SM_DONE + (tid - 32) * 8, 1);
    __syncthreads();
    uint32_t tmem;
    asm volatile("ld.shared.b32 %0, [%1];" : "=r"(tmem) : "r"(sb + SM_TMEMPTR));

    if (wid < 4) {
        // ---- A loader: thread owns M row m0+tid; LDG -> regs -> TMEM ----
        int mrow = m0 + tid; if (mrow >= M) mrow = M - 1;
        const int bbA = mrow / HWp; const int remA = mrow - bbA * HWp;
        const int tyA = remA / Wp;  const int txA = remA - tyA * Wp;
        const size_t arow = ((size_t)(bbA * H + tyA + a) * W + txA + bt) * Cin;

        for (int sl = 0; sl < NSLOT; ++sl) {
            const int s3 = sl % 3;
            if (sl >= 3) mbar_wait(sb + SM_DONE + s3 * 8, (uint32_t)(((sl / 3) - 1) & 1));
            const int chunk = sl >> 1, half = sl & 1;
            const bf16* pa = (half ? Al : Ah) + arow + chunk * 64;
            uint32_t regs[32];
#pragma unroll
            for (int j = 0; j < 8; ++j) {
                const uint4 v = *(const uint4*)(pa + 8 * j);
                regs[4 * j + 0] = v.x; regs[4 * j + 1] = v.y;
                regs[4 * j + 2] = v.z; regs[4 * j + 3] = v.w;
            }
            TCGEN05_ST_X32(tmem + TM_A + s3 * 32 + ((uint32_t)wid << 21), regs);
            TCGEN05_WAIT_ST();
            TCGEN05_FENCE_BEFORE();
            MBARRIER_ARRIVE(sb + SM_FULL + s3 * 8);
        }
    } else if (wid < 8) {
        // ---- B loader: thread owns rows r2 and r2+128 ----
        const int r2 = tid - 128;
        const size_t brow0 = ((size_t)((kh * 4 + kw) * COUT + r2)) * Cin;
        const size_t brow1 = ((size_t)((kh * 4 + kw) * COUT + r2 + 128)) * Cin;
        uint32_t sw0[8], sw1[8];
#pragma unroll
        for (int j = 0; j < 8; ++j) {
            sw0[j] = SWZ((uint32_t)(r2 * 128 + 16 * j));
            sw1[j] = SWZ((uint32_t)((r2 + 128) * 128 + 16 * j));
        }
        for (int sl = 0; sl < NSLOT; ++sl) {
            const int s3 = sl % 3;
            if (sl >= 3) mbar_wait(sb + SM_DONE + s3 * 8, (uint32_t)(((sl / 3) - 1) & 1));
            const int chunk = sl >> 1, half = sl & 1;
            const bf16* pb0 = (half ? Wl : Wh) + brow0 + chunk * 64;
            const bf16* pb1 = (half ? Wl : Wh) + brow1 + chunk * 64;
            const uint32_t stgo = SL_STAGE0 + s3 * SLOT_BYTES;
#pragma unroll
            for (int j = 0; j < 8; ++j) {
                *(uint4*)(smem + stgo + sw0[j]) = *(const uint4*)(pb0 + 8 * j);
                *(uint4*)(smem + stgo + sw1[j]) = *(const uint4*)(pb1 + 8 * j);
            }
            FENCE_ASYNC_SHARED();
            MBARRIER_ARRIVE(sb + SM_FULL + s3 * 8);
        }
    } else {
        // ---- MMA issuer ----
        if (elect_one()) {
            for (int i = 0; i < NK; ++i) {
                const int jh = 2 * i, jl = 2 * i + 1;
                const int sh = jh % 3, slx = jl % 3;
                mbar_wait(sb + SM_FULL + sh * 8, (uint32_t)((jh / 3) & 1));
                mbar_wait(sb + SM_FULL + slx * 8, (uint32_t)((jl / 3) & 1));
                TCGEN05_FENCE_AFTER();
                const uint32_t aHi = tmem + TM_A + sh * 32;
                const uint32_t aLo = tmem + TM_A + slx * 32;
                const uint64_t dBh = MAKE_DESC(sb + SL_STAGE0 + sh * SLOT_BYTES);
                const uint64_t dBl = MAKE_DESC(sb + SL_STAGE0 + slx * SLOT_BYTES);
#pragma unroll
                for (int ks = 0; ks < 4; ++ks) {
                    const uint32_t en = (i > 0 || ks > 0) ? 1u : 0u;
                    mma_bf16_ts(tmem + TM_D, aHi + ks * 8, dBh + ks * 2, en);
                    mma_bf16_ts(tmem + TM_D, aHi + ks * 8, dBl + ks * 2, 1u);
                    mma_bf16_ts(tmem + TM_D, aLo + ks * 8, dBh + ks * 2, 1u);
                }
                TCGEN05_COMMIT(sb + SM_DONE + sh * 8);
                TCGEN05_COMMIT(sb + SM_DONE + slx * 8);
            }
        }
    }

    {
        const int jlast = NSLOT - 1;
        mbar_wait(sb + SM_DONE + (jlast % 3) * 8, (uint32_t)((jlast / 3) & 1));
    }
    TCGEN05_FENCE_AFTER();
    __syncthreads();

    if (wid < 4) {
        const int m = m0 + wid * 32 + lane;
        const bool valid = (m < M);
        float* pb = part + (((size_t)(tap * 4 + phase) * L1_MPAD + m) * COUT);
#pragma unroll
        for (int q = 0; q < 8; ++q) {
            const int c0 = q * 32;
            uint32_t regs[32];
            TCGEN05_LD_X32(regs, tmem + TM_D + c0);
            TCGEN05_WAIT_LD();
            if (valid) {
#pragma unroll
                for (int k4 = 0; k4 < 8; ++k4) {
                    float4 v;
                    v.x = __uint_as_float(regs[k4 * 4 + 0]);
                    v.y = __uint_as_float(regs[k4 * 4 + 1]);
                    v.z = __uint_as_float(regs[k4 * 4 + 2]);
                    v.w = __uint_as_float(regs[k4 * 4 + 3]);
                    *(float4*)(pb + c0 + k4 * 4) = v;
                }
            }
        }
    }

    __syncthreads();
    if (tid < 3) MBARRIER_INVAL(sb + SM_FULL + tid * 8);
    else if (tid >= 32 && tid < 35) MBARRIER_INVAL(sb + SM_DONE + (tid - 32) * 8);
    __syncthreads();
    if (wid == 0) TCGEN05_DEALLOC(tmem, 512);
#else
    const int tid = threadIdx.x;
    const int phase = blockIdx.y;
    const int py = phase >> 1, px = phase & 1;
    const int tap = blockIdx.z;
    const int a = tap >> 1, bt = tap & 1;
    const int kh = 2 * a + 1 - py, kw = 2 * bt + 1 - px;
    const int m0 = blockIdx.x * 128;
    for (int idx = tid; idx < 128 * 256; idx += NTHR) {
        const int ml = idx >> 8, n = idx & 255;
        const int m = m0 + ml;
        if (m >= M) continue;
        const int bb = m / HWp; const int rem = m - bb * HWp;
        const int ty = rem / Wp; const int tx = rem - ty * Wp;
        const bf16* ah = Ah + ((size_t)(bb * H + ty + a) * W + tx + bt) * Cin;
        const bf16* al = Al + ((size_t)(bb * H + ty + a) * W + tx + bt) * Cin;
        const bf16* wh = Wh + ((size_t)((kh * 4 + kw) * COUT + n)) * Cin;
        const bf16* wl = Wl + ((size_t)((kh * 4 + kw) * COUT + n)) * Cin;
        float acc = 0.f;
        for (int c = 0; c < Cin; ++c) {
            const float av = __bfloat162float(ah[c]) + __bfloat162float(al[c]);
            const float wv = __bfloat162float(wh[c]) + __bfloat162float(wl[c]);
            acc = fmaf(av, wv, acc);
        }
        part[(((size_t)(tap * 4 + phase) * L1_MPAD + m) * COUT) + n] = acc;
    }
#endif
}

// Reduce L1 partials: sum 4 taps, BN + ReLU, bf16 hi/lo split, scatter NHWC.
__global__ __launch_bounds__(256)
void reduce_l1(const float* __restrict__ part,
               const float* __restrict__ gma, const float* __restrict__ bta,
               const float* __restrict__ mu,  const float* __restrict__ var,
               bf16* __restrict__ Yh, bf16* __restrict__ Yl)
{
    const int t = blockIdx.x * 256 + threadIdx.x;
    if (t >= 4 * L1_M * 64) return;
    const int n4 = t & 63;
    const int rest = t >> 6;
    const int m = rest % L1_M;
    const int phase = rest / L1_M;
    const int py = phase >> 1, px = phase & 1;

    float4 acc = make_float4(0.f, 0.f, 0.f, 0.f);
#pragma unroll
    for (int tap = 0; tap < 4; ++tap) {
        const float4 v = *(const float4*)(part + ((size_t)(tap * 4 + phase) * L1_MPAD + m) * COUT + n4 * 4);
        acc.x += v.x; acc.y += v.y; acc.z += v.z; acc.w += v.w;
    }
    const int c = n4 * 4;
    float vv[4] = {acc.x, acc.y, acc.z, acc.w};
    bf16 hb[4], lb[4];
#pragma unroll
    for (int e = 0; e < 4; ++e) {
        const float s = gma[c + e] * rsqrtf(var[c + e] + BN_EPS);
        const float bi = bta[c + e] - mu[c + e] * s;
        const float v = fmaxf(fmaf(vv[e], s, bi), 0.f);
        split_bf(v, hb[e], lb[e]);
    }
    const int bb = m / 35; const int rem = m - bb * 35;
    const int ty = rem / 5; const int tx = rem - ty * 5;
    const int oy = 2 * ty + py, ox = 2 * tx + px;
    const size_t o = ((size_t)(bb * 14 + oy) * 10 + ox) * COUT + c;
    *(__nv_bfloat162*)(Yh + o)     = __nv_bfloat162(hb[0], hb[1]);
    *(__nv_bfloat162*)(Yh + o + 2) = __nv_bfloat162(hb[2], hb[3]);
    *(__nv_bfloat162*)(Yl + o)     = __nv_bfloat162(lb[0], lb[1]);
    *(__nv_bfloat162*)(Yl + o + 2) = __nv_bfloat162(lb[2], lb[3]);
}

// ===========================================================================
// Kernel B: M=128 x N=256 TS tiles for L2/L3 (Cin=256, K=1024, NK=16).
// mode 1: BN+ReLU bf16 hi/lo store (L2).
// mode 0: BN+ReLU + fused 1x1 conv (256->17)+bias -> transposed heatmap (L3).
// ===========================================================================
__global__ __launch_bounds__(NTHR, 1)
void deconv_tc2(const bf16* __restrict__ Ah, const bf16* __restrict__ Al,
                const bf16* __restrict__ Wh, const bf16* __restrict__ Wl,
                const float* __restrict__ gma, const float* __restrict__ bta,
                const float* __restrict__ mu,  const float* __restrict__ var,
                bf16* __restrict__ Yh, bf16* __restrict__ Yl,
                const float* __restrict__ wfp, const float* __restrict__ bfp,
                float* __restrict__ hmp,
                int H, int W, int Cin, int mode)
{
#if TCPATH
    extern __shared__ char smem[];
    const uint32_t sb = smem_u32(smem);
    const int tid = threadIdx.x;
    const int wid = tid >> 5, lane = tid & 31;

    const int phase = blockIdx.y;
    const int py = phase >> 1, px = phase & 1;
    const int m0 = blockIdx.x * 128;
    const int Hp = H - 1, Wp = W - 1;
    const int HWp = Hp * Wp;
    const int M = BDIM_B * HWp;
    const int NK = Cin >> 4;               // (4*Cin)/64 = 16
    const int NSLOT = 2 * NK;

    if (wid == 0) { TCGEN05_ALLOC(sb + SM_TMEMPTR, 512); TCGEN05_RELINQ(); }
    if (tid < 256) {
        const float s = gma[tid] * rsqrtf(var[tid] + BN_EPS);
        ((float*)(smem + SM_SC))[tid] = s;
        ((float*)(smem + SM_BI))[tid] = bta[tid] - mu[tid] * s;
    }
    if (mode == 0) {
        for (int i = tid; i < COUT * KPT; i += NTHR)
            ((float*)(smem + SM_WF))[i] = wfp[i];
    }
    if (tid < 3) MBARRIER_INIT(sb + SM_FULL + tid * 8, 256);
    else if (tid >= 32 && tid < 35) MBARRIER_INIT(sb + SM_DONE + (tid - 32) * 8, 1);
    __syncthreads();
    uint32_t tmem;
    asm volatile("ld.shared.b32 %0, [%1];" : "=r"(tmem) : "r"(sb + SM_TMEMPTR));

    if (wid < 4) {
        // ---- A loader: thread owns M row m0+tid ----
        int mrow = m0 + tid; if (mrow >= M) mrow = M - 1;
        const int bbA = mrow / HWp; const int remA = mrow - bbA * HWp;
        const int tyA = remA / Wp;  const int txA = remA - tyA * Wp;
        const size_t arow = ((size_t)(bbA * H + tyA) * W + txA) * Cin;

        for (int sl = 0; sl < NSLOT; ++sl) {
            const int s3 = sl % 3;
            if (sl >= 3) mbar_wait(sb + SM_DONE + s3 * 8, (uint32_t)(((sl / 3) - 1) & 1));
            const int chunk = sl >> 1, half = sl & 1;
            const int kt = chunk * 64;
            const int tap = kt / Cin;
            const int ci0 = kt - tap * Cin;
            const int a = tap >> 1, bt = tap & 1;
            const bf16* pa = (half ? Al : Ah) + arow + (size_t)(a * W + bt) * Cin + ci0;
            uint32_t regs[32];
#pragma unroll
            for (int j = 0; j < 8; ++j) {
                const uint4 v = *(const uint4*)(pa + 8 * j);
                regs[4 * j + 0] = v.x; regs[4 * j + 1] = v.y;
                regs[4 * j + 2] = v.z; regs[4 * j + 3] = v.w;
            }
            TCGEN05_ST_X32(tmem + TM_A + s3 * 32 + ((uint32_t)wid << 21), regs);
            TCGEN05_WAIT_ST();
            TCGEN05_FENCE_BEFORE();
            MBARRIER_ARRIVE(sb + SM_FULL + s3 * 8);
        }
    } else if (wid < 8) {
        // ---- B loader: thread owns rows r2 and r2+128 ----
        const int r2 = tid - 128;
        uint32_t sw0[8], sw1[8];
#pragma unroll
        for (int j = 0; j < 8; ++j) {
            sw0[j] = SWZ((uint32_t)(r2 * 128 + 16 * j));
            sw1[j] = SWZ((uint32_t)((r2 + 128) * 128 + 16 * j));
        }
        for (int sl = 0; sl < NSLOT; ++sl) {
            const int s3 = sl % 3;
            if (sl >= 3) mbar_wait(sb + SM_DONE + s3 * 8, (uint32_t)(((sl / 3) - 1) & 1));
            const int chunk = sl >> 1, half = sl & 1;
            const int kt = chunk * 64;
            const int tap = kt / Cin;
            const int ci0 = kt - tap * Cin;
            const int a = tap >> 1, bt = tap & 1;
            const int kh = 2 * a + 1 - py, kw = 2 * bt + 1 - px;
            const bf16* base = (half ? Wl : Wh) + (size_t)(kh * 4 + kw) * COUT * Cin + ci0;
            const bf16* pb0 = base + (size_t)r2 * Cin;
            const bf16* pb1 = base + (size_t)(r2 + 128) * Cin;
            const uint32_t stgo = SL_STAGE0 + s3 * SLOT_BYTES;
#pragma unroll
            for (int j = 0; j < 8; ++j) {
                *(uint4*)(smem + stgo + sw0[j]) = *(const uint4*)(pb0 + 8 * j);
                *(uint4*)(smem + stgo + sw1[j]) = *(const uint4*)(pb1 + 8 * j);
            }
            FENCE_ASYNC_SHARED();
            MBARRIER_ARRIVE(sb + SM_FULL + s3 * 8);
        }
    } else {
        // ---- MMA issuer ----
        if (elect_one()) {
            for (int i = 0; i < NK; ++i) {
                const int jh = 2 * i, jl = 2 * i + 1;
                const int sh = jh % 3, slx = jl % 3;
                mbar_wait(sb + SM_FULL + sh * 8, (uint32_t)((jh / 3) & 1));
                mbar_wait(sb + SM_FULL + slx * 8, (uint32_t)((jl / 3) & 1));
                TCGEN05_FENCE_AFTER();
                const uint32_t aHi = tmem + TM_A + sh * 32;
                const uint32_t aLo = tmem + TM_A + slx * 32;
                const uint64_t dBh = MAKE_DESC(sb + SL_STAGE0 + sh * SLOT_BYTES);
                const uint64_t dBl = MAKE_DESC(sb + SL_STAGE0 + slx * SLOT_BYTES);
#pragma unroll
                for (int ks = 0; ks < 4; ++ks) {
                    const uint32_t en = (i > 0 || ks > 0) ? 1u : 0u;
                    mma_bf16_ts(tmem + TM_D, aHi + ks * 8, dBh + ks * 2, en);
                    mma_bf16_ts(tmem + TM_D, aHi + ks * 8, dBl + ks * 2, 1u);
                    mma_bf16_ts(tmem + TM_D, aLo + ks * 8, dBh + ks * 2, 1u);
                }
                TCGEN05_COMMIT(sb + SM_DONE + sh * 8);
                TCGEN05_COMMIT(sb + SM_DONE + slx * 8);
            }
        }
    }

    {
        const int jlast = NSLOT - 1;
        mbar_wait(sb + SM_DONE + (jlast % 3) * 8, (uint32_t)((jlast / 3) & 1));
    }
    TCGEN05_FENCE_AFTER();
    __syncthreads();

    if (wid < 4) {
        const float* scs = (const float*)(smem + SM_SC);
        const float* bis = (const float*)(smem + SM_BI);
        const float* wfs = (const float*)(smem + SM_WF);
        const int m = m0 + wid * 32 + lane;
        const bool valid = (m < M);
        int bb = 0, ty = 0, tx = 0;
        if (valid) { bb = m / HWp; const int rem = m - bb * HWp; ty = rem / Wp; tx = rem - ty * Wp; }
        const int H2 = 2 * H - 2, W2 = 2 * W - 2;
        const int oy = 2 * ty + py, ox = 2 * tx + px;

        float hacc[KPT];
        if (mode == 0) {
#pragma unroll
            for (int k = 0; k < KPT; ++k) hacc[k] = bfp[k];
        }
        const size_t obase = ((size_t)(bb * H2 + oy) * W2 + ox) * COUT;

#pragma unroll
        for (int q = 0; q < 8; ++q) {
            const int c0 = q * 32;
            uint32_t regs[32];
            TCGEN05_LD_X32(regs, tmem + TM_D + c0);
            TCGEN05_WAIT_LD();
            if (valid) {
                if (mode == 0) {
#pragma unroll
                    for (int e = 0; e < 32; ++e) {
                        const int c = c0 + e;
                        const float v = fmaxf(fmaf(__uint_as_float(regs[e]), scs[c], bis[c]), 0.f);
                        const float* wr = wfs + c * KPT;
#pragma unroll
                        for (int k = 0; k < KPT; ++k)
                            hacc[k] = fmaf(v, wr[k], hacc[k]);
                    }
                } else {
#pragma unroll
                    for (int k4 = 0; k4 < 8; ++k4) {
                        bf16 hb[4], lb[4];
#pragma unroll
                        for (int e = 0; e < 4; ++e) {
                            const int c = c0 + k4 * 4 + e;
                            const float v = fmaxf(fmaf(__uint_as_float(regs[k4 * 4 + e]), scs[c], bis[c]), 0.f);
                            split_bf(v, hb[e], lb[e]);
                        }
                        const size_t o = obase + c0 + k4 * 4;
                        *(__nv_bfloat162*)(Yh + o)     = __nv_bfloat162(hb[0], hb[1]);
                        *(__nv_bfloat162*)(Yh + o + 2) = __nv_bfloat162(hb[2], hb[3]);
                        *(__nv_bfloat162*)(Yl + o)     = __nv_bfloat162(lb[0], lb[1]);
                        *(__nv_bfloat162*)(Yl + o + 2) = __nv_bfloat162(lb[2], lb[3]);
                    }
                }
            }
        }
        if (mode == 0 && valid) {
            const int pp = oy * WD + ox;
            float* hb = hmp + (size_t)bb * KPT * HWD + pp;
#pragma unroll
            for (int k = 0; k < KPT; ++k)
                hb[(size_t)k * HWD] = hacc[k];
        }
    }

    __syncthreads();
    if (tid < 3) MBARRIER_INVAL(sb + SM_FULL + tid * 8);
    else if (tid >= 32 && tid < 35) MBARRIER_INVAL(sb + SM_DONE + (tid - 32) * 8);
    __syncthreads();
    if (wid == 0) TCGEN05_DEALLOC(tmem, 512);
#else
    // ------------------ fallback (non-accelerated pass) --------------------
    const int tid = threadIdx.x;
    const int phase = blockIdx.y;
    const int py = phase >> 1, px = phase & 1;
    const int m0 = blockIdx.x * 128;
    const int Hp = H - 1, Wp = W - 1;
    const int HWp = Hp * Wp;
    const int M = BDIM_B * HWp;
    const int H2 = 2 * H - 2, W2 = 2 * W - 2;

    if (mode == 1) {
        for (int idx = tid; idx < 128 * 256; idx += NTHR) {
            const int ml = idx >> 8, n = idx & 255;
            const int m = m0 + ml;
            if (m >= M) continue;
            const int bb = m / HWp; const int rem = m - bb * HWp;
            const int ty = rem / Wp; const int tx = rem - ty * Wp;
            float acc = 0.f;
            for (int tap = 0; tap < 4; ++tap) {
                const int a = tap >> 1, bt = tap & 1;
                const int kh = 2 * a + 1 - py, kw = 2 * bt + 1 - px;
                const bf16* ah = Ah + ((size_t)(bb * H + ty + a) * W + tx + bt) * Cin;
                const bf16* al = Al + ((size_t)(bb * H + ty + a) * W + tx + bt) * Cin;
                const bf16* wh = Wh + ((size_t)((kh * 4 + kw) * COUT + n)) * Cin;
                const bf16* wl = Wl + ((size_t)((kh * 4 + kw) * COUT + n)) * Cin;
                for (int c = 0; c < Cin; ++c) {
                    const float av = __bfloat162float(ah[c]) + __bfloat162float(al[c]);
                    const float wv = __bfloat162float(wh[c]) + __bfloat162float(wl[c]);
                    acc = fmaf(av, wv, acc);
                }
            }
            const float s = gma[n] * rsqrtf(var[n] + BN_EPS);
            float v = fmaxf(fmaf(acc - mu[n], s, bta[n]), 0.f);
            const int oy = 2 * ty + py, ox = 2 * tx + px;
            const size_t o = ((size_t)(bb * H2 + oy) * W2 + ox) * COUT + n;
            bf16 h, l; split_bf(v, h, l);
            Yh[o] = h; Yl[o] = l;
        }
    } else {
        for (int ml = tid; ml < 128; ml += NTHR) {
            const int m = m0 + ml;
            if (m >= M) continue;
            const int bb = m / HWp; const int rem = m - bb * HWp;
            const int ty = rem / Wp; const int tx = rem - ty * Wp;
            float hacc[KPT];
            for (int k = 0; k < KPT; ++k) hacc[k] = bfp[k];
            for (int n = 0; n < COUT; ++n) {
                float acc = 0.f;
                for (int tap = 0; tap < 4; ++tap) {
                    const int a = tap >> 1, bt = tap & 1;
                    const int kh = 2 * a + 1 - py, kw = 2 * bt + 1 - px;
                    const bf16* ah = Ah + ((size_t)(bb * H + ty + a) * W + tx + bt) * Cin;
                    const bf16* al = Al + ((size_t)(bb * H + ty + a) * W + tx + bt) * Cin;
                    const bf16* wh = Wh + ((size_t)((kh * 4 + kw) * COUT + n)) * Cin;
                    const bf16* wl = Wl + ((size_t)((kh * 4 + kw) * COUT + n)) * Cin;
                    for (int c = 0; c < Cin; ++c) {
                        const float av = __bfloat162float(ah[c]) + __bfloat162float(al[c]);
                        const float wv = __bfloat162float(wh[c]) + __bfloat162float(wl[c]);
                        acc = fmaf(av, wv, acc);
                    }
                }
                const float s = gma[n] * rsqrtf(var[n] + BN_EPS);
                const float v = fmaxf(fmaf(acc - mu[n], s, bta[n]), 0.f);
                for (int k = 0; k < KPT; ++k)
                    hacc[k] = fmaf(v, wfp[n * KPT + k], hacc[k]);
            }
            const int oy = 2 * ty + py, ox = 2 * tx + px;
            const int pp = oy * WD + ox;
            for (int k = 0; k < KPT; ++k)
                hmp[(size_t)(bb * KPT + k) * HWD + pp] = hacc[k];
        }
    }
#endif
}

// ---------------------------------------------------------------------------
// Per-(b,k) argmax + subpixel refinement.
// ---------------------------------------------------------------------------
__global__ void detect_kernel(const float* __restrict__ hm, float* __restrict__ out)
{
    const float* row = hm + (size_t)blockIdx.x * HWD;
    const int tid = threadIdx.x;

    float best = -3.402823466e+38f; int bidx = 0x7fffffff;
    for (int i = tid; i < HWD; i += 128) {
        const float v = row[i];
        if (v > best) { best = v; bidx = i; }
    }
    __shared__ float sv[128];
    __shared__ int   si[128];
    sv[tid] = best; si[tid] = bidx;
    __syncthreads();
    for (int s = 64; s > 0; s >>= 1) {
        if (tid < s) {
            const float v2 = sv[tid + s]; const int i2 = si[tid + s];
            if (v2 > sv[tid] || (v2 == sv[tid] && i2 < si[tid])) { sv[tid] = v2; si[tid] = i2; }
        }
        __syncthreads();
    }
    if (tid == 0) {
        const float score = sv[0];
        const int idx = si[0];
        const bool pos = score > 0.f;
        const int pxi = pos ? (idx % WD) : 0;
        const int pyi = pos ? (idx / WD) : 0;
        const bool inner = (pxi > 0) && (pxi < WD - 1) && (pyi > 0) && (pyi < HD - 1);
        float dx = 0.f, dy = 0.f;
        if (inner) {
            const int base = pyi * WD + pxi;
            const float d1 = row[base + 1]  - row[base - 1];
            const float d2 = row[base + WD] - row[base - WD];
            dx = (d1 > 0.f) ? 0.25f : ((d1 < 0.f) ? -0.25f : 0.f);
            dy = (d2 > 0.f) ? 0.25f : ((d2 < 0.f) ? -0.25f : 0.f);
        }
        float* o = out + (size_t)blockIdx.x * 3;
        o[0] = (float)pxi + dx;
        o[1] = (float)pyi + dy;
        o[2] = score;
    }
}

// ---------------------------------------------------------------------------
extern "C" void kernel_launch(void* const* d_in, const int* in_sizes, int n_in,
                              void* d_out, int out_size)
{
    const float* x  = (const float*)d_in[0];
    const float* w1 = (const float*)d_in[1];
    const float* g1 = (const float*)d_in[2];
    const float* b1 = (const float*)d_in[3];
    const float* m1 = (const float*)d_in[4];
    const float* v1 = (const float*)d_in[5];
    const float* w2 = (const float*)d_in[6];
    const float* g2 = (const float*)d_in[7];
    const float* b2 = (const float*)d_in[8];
    const float* m2 = (const float*)d_in[9];
    const float* v2 = (const float*)d_in[10];
    const float* w3 = (const float*)d_in[11];
    const float* g3 = (const float*)d_in[12];
    const float* b3 = (const float*)d_in[13];
    const float* m3 = (const float*)d_in[14];
    const float* v3 = (const float*)d_in[15];
    const float* wf = (const float*)d_in[16];
    const float* bf = (const float*)d_in[17];
    float* out = (float*)d_out;

    bf16 *xh, *xl, *w1h, *w1l, *w2h, *w2l, *w3h, *w3l, *y1h, *y1l, *y2h, *y2l;
    float *p1, *hm;
    cudaGetSymbolAddress((void**)&xh,  g_xh);
    cudaGetSymbolAddress((void**)&xl,  g_xl);
    cudaGetSymbolAddress((void**)&w1h, g_w1h);
    cudaGetSymbolAddress((void**)&w1l, g_w1l);
    cudaGetSymbolAddress((void**)&w2h, g_w2h);
    cudaGetSymbolAddress((void**)&w2l, g_w2l);
    cudaGetSymbolAddress((void**)&w3h, g_w3h);
    cudaGetSymbolAddress((void**)&w3l, g_w3l);
    cudaGetSymbolAddress((void**)&p1,  g_p1);
    cudaGetSymbolAddress((void**)&y1h, g_y1h);
    cudaGetSymbolAddress((void**)&y1l, g_y1l);
    cudaGetSymbolAddress((void**)&y2h, g_y2h);
    cudaGetSymbolAddress((void**)&y2l, g_y2l);
    cudaGetSymbolAddress((void**)&hm,  g_hm);

    static bool attr_done = false;
    if (!attr_done) {
        cudaFuncSetAttribute(deconv_tc1s, cudaFuncAttributeMaxDynamicSharedMemorySize, SMEM2_TOTAL);
        cudaFuncSetAttribute(deconv_tc2,  cudaFuncAttributeMaxDynamicSharedMemorySize, SMEM2_TOTAL);
        attr_done = true;
    }

    // preprocess + L1 (tc1s kept in the profiled launch slot)
    split_kernel<<<4096, 256>>>(x, xh, xl, BDIM_B * 8 * 6 * 2048);
    wtrans_kernel<<<dim3(2048 / 32, COUT / 32, 16), dim3(32, 8)>>>(w1, w1h, w1l, 2048);
    wtrans_kernel<<<dim3(256 / 32,  COUT / 32, 16), dim3(32, 8)>>>(w2, w2h, w2l, 256);
    deconv_tc1s<<<dim3(18, 4, 4), NTHR, SMEM2_TOTAL>>>(xh, xl, w1h, w1l, p1);
    wtrans_kernel<<<dim3(256 / 32,  COUT / 32, 16), dim3(32, 8)>>>(w3, w3h, w3l, 256);
    reduce_l1<<<(4 * L1_M * 64 + 255) / 256, 256>>>(p1, g1, b1, m1, v1, y1h, y1l);

    // L2: M_phase = 7488 -> 59 M128 tiles
    deconv_tc2<<<dim3(59, 4), NTHR, SMEM2_TOTAL>>>(y1h, y1l, w2h, w2l, g2, b2, m2, v2,
                                                   y2h, y2l, nullptr, nullptr, nullptr,
                                                   14, 10, 256, 1);
    // L3 + fused heatmap: M_phase = 27200 -> 213 M128 tiles
    deconv_tc2<<<dim3(213, 4), NTHR, SMEM2_TOTAL>>>(y2h, y2l, w3h, w3l, g3, b3, m3, v3,
                                                    nullptr, nullptr, wf, bf, hm,
                                                    26, 18, 256, 0);
    // argmax + subpixel per (b, keypoint)
    detect_kernel<<<BDIM_B * KPT, 128>>>(hm, out);
}

// round 15
// speedup vs baseline: 2.0527x; 2.0527x over previous
#include <cuda_runtime.h>
#include <cuda_bf16.h>
#include <cstdint>

// ---------------------------------------------------------------------------
// SimplePose via tcgen05 bf16 hi/lo 3-pass GEMMs (fp32-near precision).
//   3x (conv_transpose k4 s2 pads(1,1) + BN + ReLU) -> 1x1 conv -> argmax det
// Phase decomposition (py,px): kh = 2a+1-py, iy = ty+a  -> dense GEMM
//   M = B*(H-1)*(W-1), K = 4*Cin, N = 256 per phase.
// Emulation: v = hi + lo with hi = bf16(v), lo = bf16(v - hi).
//   C = Ah*Bh + Ah*Bl + Al*Bh  (3 bf16 tcgen05 passes, fp32 TMEM accum)
//
// Round 15: revert TS (regressed); round-13 SS structure with COALESCED
// loaders: 8 threads per 128B row (seg = tid&7, row = tid>>3 + 32j) so each
// warp LDG instruction covers 4 full cache lines (4 wavefronts, was 16).
// Attacks the measured L1TEX 81.6% bottleneck with zero protocol change.
// ---------------------------------------------------------------------------

#if defined(__CUDA_ARCH_FEAT_SM103_ALL) || defined(__CUDA_ARCH_FEAT_SM100_ALL)
#define TCPATH 1
#else
#define TCPATH 0
#endif

#define BDIM_B   64
#define COUT     256
#define KPT      17
#define BN_EPS   1e-5f
#define HD 50
#define WD 34
#define HWD (HD * WD)          // 1700
#define NTHR 288               // 8 loader warps + 1 MMA warp

#define L1_MPAD 2304
#define L1_M 2240              // 64 * 7 * 5

typedef __nv_bfloat16 bf16;

// ---------------- scratch (static; cudaMalloc forbidden) -------------------
__device__ bf16  g_xh[BDIM_B * 8 * 6 * 2048];
__device__ bf16  g_xl[BDIM_B * 8 * 6 * 2048];
__device__ bf16  g_w1h[16 * COUT * 2048];
__device__ bf16  g_w1l[16 * COUT * 2048];
__device__ bf16  g_w2h[16 * COUT * 256];
__device__ bf16  g_w2l[16 * COUT * 256];
__device__ bf16  g_w3h[16 * COUT * 256];
__device__ bf16  g_w3l[16 * COUT * 256];
__device__ float g_p1 [4 * 4 * L1_MPAD * COUT];
__device__ bf16  g_y1h[BDIM_B * 14 * 10 * COUT];
__device__ bf16  g_y1l[BDIM_B * 14 * 10 * COUT];
__device__ bf16  g_y2h[BDIM_B * 26 * 18 * COUT];
__device__ bf16  g_y2l[BDIM_B * 26 * 18 * COUT];
__device__ float g_hm [BDIM_B * KPT * HWD];

// ---------------------------- helpers --------------------------------------
__device__ __forceinline__ void split_bf(float v, bf16& h, bf16& l) {
    h = __float2bfloat16_rn(v);
    l = __float2bfloat16_rn(v - __bfloat162float(h));
}

#if TCPATH
__device__ __forceinline__ uint32_t smem_u32(const void* p) {
    uint32_t a;
    asm("{ .reg .u64 t; cvta.to.shared.u64 t, %1; cvt.u32.u64 %0, t; }" : "=r"(a) : "l"(p));
    return a;
}
__device__ __forceinline__ uint32_t elect_one() {
    uint32_t pr;
    asm volatile("{\n\t.reg .pred p;\n\telect.sync _|p, 0xFFFFFFFF;\n\tselp.b32 %0, 1, 0, p;\n\t}" : "=r"(pr));
    return pr;
}

#define MBARRIER_INIT(addr, cnt) \
    asm volatile("mbarrier.init.shared.b64 [%0], %1;" :: "r"(addr), "r"(cnt) : "memory")
#define MBARRIER_INVAL(addr) \
    asm volatile("mbarrier.inval.shared.b64 [%0];" :: "r"(addr) : "memory")
#define MBARRIER_ARRIVE(addr) \
    asm volatile("mbarrier.arrive.release.cta.shared::cta.b64 _, [%0];" :: "r"(addr) : "memory")
__device__ __forceinline__ void mbar_wait(uint32_t mbar, uint32_t parity) {
    asm volatile(
        "{\n\t.reg .pred P;\n\t"
        "WL%=:\n\t"
        "mbarrier.try_wait.parity.acquire.cta.shared::cta.b64 P, [%0], %1, 0x989680;\n\t"
        "@P bra.uni WD%=;\n\t"
        "bra.uni WL%=;\n\t"
        "WD%=:\n\t}"
        :: "r"(mbar), "r"(parity) : "memory");
}
#define TCGEN05_ALLOC(sm, n) \
    asm volatile("tcgen05.alloc.cta_group::1.sync.aligned.shared::cta.b32 [%0], %1;" :: "r"(sm), "r"(n) : "memory")
#define TCGEN05_DEALLOC(tm, n) \
    asm volatile("tcgen05.dealloc.cta_group::1.sync.aligned.b32 %0, %1;" :: "r"(tm), "r"(n))
#define TCGEN05_RELINQ() \
    asm volatile("tcgen05.relinquish_alloc_permit.cta_group::1.sync.aligned;")
#define TCGEN05_COMMIT(mb) \
    asm volatile("tcgen05.commit.cta_group::1.mbarrier::arrive::one.shared::cluster.b64 [%0];" :: "r"(mb) : "memory")
#define TCGEN05_FENCE_AFTER() \
    asm volatile("tcgen05.fence::after_thread_sync;" ::: "memory")
#define TCGEN05_WAIT_LD() \
    asm volatile("tcgen05.wait::ld.sync.aligned;" ::: "memory")
#define FENCE_ASYNC_SHARED() \
    asm volatile("fence.proxy.async.shared::cta;" ::: "memory")

#define TCGEN05_LD_X32(r, tm) \
    asm volatile( \
        "tcgen05.ld.sync.aligned.32x32b.x32.b32 " \
        "{%0, %1, %2, %3, %4, %5, %6, %7, " \
        " %8, %9, %10, %11, %12, %13, %14, %15, " \
        " %16, %17, %18, %19, %20, %21, %22, %23, " \
        " %24, %25, %26, %27, %28, %29, %30, %31}, [%32];" \
        : "=r"((r)[0]),  "=r"((r)[1]),  "=r"((r)[2]),  "=r"((r)[3]), \
          "=r"((r)[4]),  "=r"((r)[5]),  "=r"((r)[6]),  "=r"((r)[7]), \
          "=r"((r)[8]),  "=r"((r)[9]),  "=r"((r)[10]), "=r"((r)[11]), \
          "=r"((r)[12]), "=r"((r)[13]), "=r"((r)[14]), "=r"((r)[15]), \
          "=r"((r)[16]), "=r"((r)[17]), "=r"((r)[18]), "=r"((r)[19]), \
          "=r"((r)[20]), "=r"((r)[21]), "=r"((r)[22]), "=r"((r)[23]), \
          "=r"((r)[24]), "=r"((r)[25]), "=r"((r)[26]), "=r"((r)[27]), \
          "=r"((r)[28]), "=r"((r)[29]), "=r"((r)[30]), "=r"((r)[31]) \
        : "r"(tm))

// SMEM descriptor (K-major SW128: LBO=1, SBO=64, version=1, layout=2)
#define SMEM_DESC_BASE \
    ((uint64_t(2) << 61) | (uint64_t(1) << 46) | (uint64_t(64) << 32) | (uint64_t(1) << 16))
#define MAKE_DESC(addr) (SMEM_DESC_BASE | ((uint64_t)((addr) >> 4) & 0x3FFF))

// bf16 MMA, cta_group::1, M=128, N=128, K=16 per issue
#define IDESC_BF16 ((1u << 4) | (1u << 7) | (1u << 10) | (16u << 17) | (8u << 24))

__device__ __forceinline__ void mma_bf16_ss(uint32_t d, uint64_t da, uint64_t db,
                                            uint32_t en) {
    asm volatile(
        "{\n\t.reg .pred p;\n\t"
        "setp.ne.u32 p, %4, 0;\n\t"
        "tcgen05.mma.cta_group::1.kind::f16 [%0], %1, %2, %3, {%5, %5, %5, %5}, p;\n\t"
        "}"
        :: "r"(d), "l"(da), "l"(db), "r"(IDESC_BF16), "r"(en), "r"(0u)
        : "memory");
}
#endif  // TCPATH

#define SWZ(o) ((o) ^ (((o) >> 3) & 0x70))

// SMEM layout: slot = one (chunk K=64, hi-or-lo half): A 2x128 rows x 128B,
// B 2x128 rows x 128B. Ring of 3.
#define SLOT_BYTES 65536
#define OFF2_B 32768
#define SM_TMEMPTR 0
#define SM_FULL 8
#define SM_DONE 32
#define SM_SC 64
#define SM_BI (64 + 1024)
#define SL_STAGE0 4096
#define SM_WF (SL_STAGE0 + 3 * SLOT_BYTES)          // 200704: wf[256*17]
#define SMEM2_TOTAL (SM_WF + COUT * KPT * 4)         // 218112

// ---------------------------------------------------------------------------
// Preprocess
// ---------------------------------------------------------------------------
__global__ void split_kernel(const float* __restrict__ in, bf16* __restrict__ hi,
                             bf16* __restrict__ lo, int n)
{
    for (int i = blockIdx.x * blockDim.x + threadIdx.x; i < n; i += gridDim.x * blockDim.x) {
        bf16 h, l; split_bf(in[i], h, l);
        hi[i] = h; lo[i] = l;
    }
}

__global__ void wtrans_kernel(const float* __restrict__ w, bf16* __restrict__ th,
                              bf16* __restrict__ tl, int Cin)
{
    __shared__ float tile[32][33];
    const int t = blockIdx.z;
    const int ci0 = blockIdx.x * 32, co0 = blockIdx.y * 32;
    const int tx = threadIdx.x, ty = threadIdx.y;
#pragma unroll
    for (int i = 0; i < 4; ++i)
        tile[ty + 8 * i][tx] = w[((size_t)(t * Cin + ci0 + ty + 8 * i)) * COUT + co0 + tx];
    __syncthreads();
#pragma unroll
    for (int i = 0; i < 4; ++i) {
        bf16 h, l; split_bf(tile[tx][ty + 8 * i], h, l);
        const size_t o = ((size_t)(t * COUT + co0 + ty + 8 * i)) * Cin + ci0 + tx;
        th[o] = h; tl[o] = l;
    }
}

// ===========================================================================
// Kernel L1S: split-K-by-tap m-paired 256x256 GEMM for L1 (Cin=2048).
// K_tap = 2048 -> NK = 32 chunks of K64, NSLOT = 64.
// Coalesced loaders: seg = tid&7 (16B within row), row = (tid>>3) + 32*j.
// ===========================================================================
__global__ __launch_bounds__(NTHR, 1)
void deconv_tc1s(const bf16* __restrict__ Ah, const bf16* __restrict__ Al,
                 const bf16* __restrict__ Wh, const bf16* __restrict__ Wl,
                 float* __restrict__ part)
{
    const int H = 8, W = 6, Cin = 2048;
    const int Hp = 7, Wp = 5, HWp = 35;
    const int M = L1_M;
#if TCPATH
    extern __shared__ char smem[];
    const uint32_t sb = smem_u32(smem);
    const int tid = threadIdx.x;
    const int wid = tid >> 5, lane = tid & 31;

    const int phase = blockIdx.y;
    const int tap = blockIdx.z;
    const int a = tap >> 1, bt = tap & 1;
    const int py = phase >> 1, px = phase & 1;
    const int kh = 2 * a + 1 - py, kw = 2 * bt + 1 - px;
    const int m0 = blockIdx.x * 256;
    const int NK = Cin >> 6;               // 32 chunks of K=64
    const int NSLOT = 2 * NK;              // 64 slots

    if (wid == 0) { TCGEN05_ALLOC(sb + SM_TMEMPTR, 512); TCGEN05_RELINQ(); }
    if (tid < 3) MBARRIER_INIT(sb + SM_FULL + tid * 8, 256);
    else if (tid >= 32 && tid < 35) MBARRIER_INIT(sb + SM_DONE + (tid - 32) * 8, 1);
    __syncthreads();
    uint32_t tmem;
    asm volatile("ld.shared.b32 %0, [%1];" : "=r"(tmem) : "r"(sb + SM_TMEMPTR));

    if (wid < 8) {
        const int seg = tid & 7;           // 16B segment within 128B row
        const int ro  = tid >> 3;          // 0..31
        size_t arowv[8], browv[8];
        uint32_t swoA[8], swoB[8];
#pragma unroll
        for (int j = 0; j < 8; ++j) {
            const int r = ro + 32 * j;     // 0..255
            const int tile = r >> 7, rr = r & 127;
            int mrow = m0 + r; if (mrow >= M) mrow = M - 1;
            const int bbA = mrow / HWp; const int remA = mrow - bbA * HWp;
            const int tyA = remA / Wp;  const int txA = remA - tyA * Wp;
            arowv[j] = ((size_t)(bbA * H + tyA + a) * W + txA + bt) * Cin + seg * 8;
            swoA[j] = (uint32_t)(tile * 16384) + SWZ((uint32_t)(rr * 128 + seg * 16));
            browv[j] = ((size_t)((kh * 4 + kw) * COUT + r)) * Cin + seg * 8;
            swoB[j] = (uint32_t)(OFF2_B + tile * 16384) + SWZ((uint32_t)(rr * 128 + seg * 16));
        }

        for (int sl = 0; sl < NSLOT; ++sl) {
            const int s3 = sl % 3;
            if (sl >= 3) mbar_wait(sb + SM_DONE + s3 * 8, (uint32_t)(((sl / 3) - 1) & 1));
            const int chunk = sl >> 1, half = sl & 1;
            const int ci0 = chunk * 64;    // elements
            const bf16* Aarr = half ? Al : Ah;
            const bf16* Warr = half ? Wl : Wh;
            const uint32_t stgo = SL_STAGE0 + s3 * SLOT_BYTES;
#pragma unroll
            for (int j = 0; j < 8; ++j)
                *(uint4*)(smem + stgo + swoA[j]) = *(const uint4*)(Aarr + arowv[j] + ci0);
#pragma unroll
            for (int j = 0; j < 8; ++j)
                *(uint4*)(smem + stgo + swoB[j]) = *(const uint4*)(Warr + browv[j] + ci0);
            FENCE_ASYNC_SHARED();
            MBARRIER_ARRIVE(sb + SM_FULL + s3 * 8);
        }
    } else {
        if (elect_one()) {
            for (int i = 0; i < NK; ++i) {
                const int jh = 2 * i, jl = 2 * i + 1;
                const int sh = jh % 3, slx = jl % 3;
                mbar_wait(sb + SM_FULL + sh * 8, (uint32_t)((jh / 3) & 1));
                mbar_wait(sb + SM_FULL + slx * 8, (uint32_t)((jl / 3) & 1));
                const uint32_t stg_h = sb + SL_STAGE0 + sh * SLOT_BYTES;
                const uint32_t stg_l = sb + SL_STAGE0 + slx * SLOT_BYTES;
                const uint64_t dAh0 = MAKE_DESC(stg_h);
                const uint64_t dAh1 = MAKE_DESC(stg_h + 16384);
                const uint64_t dAl0 = MAKE_DESC(stg_l);
                const uint64_t dAl1 = MAKE_DESC(stg_l + 16384);
                const uint64_t dBh  = MAKE_DESC(stg_h + OFF2_B);
                const uint64_t dBl  = MAKE_DESC(stg_l + OFF2_B);
#pragma unroll
                for (int ks = 0; ks < 4; ++ks) {        // K=16 per step
#pragma unroll
                    for (int pass = 0; pass < 3; ++pass) {
                        const uint64_t da0 = (pass == 2) ? dAl0 : dAh0;
                        const uint64_t da1 = (pass == 2) ? dAl1 : dAh1;
                        const uint64_t db  = (pass == 1) ? dBl  : dBh;
                        const uint32_t en = (i > 0 || ks > 0 || pass > 0) ? 1u : 0u;
#pragma unroll
                        for (int nh = 0; nh < 2; ++nh) {
                            mma_bf16_ss(tmem + 0   + nh * 128, da0 + ks * 2, db + nh * 1024 + ks * 2, en);
                            mma_bf16_ss(tmem + 256 + nh * 128, da1 + ks * 2, db + nh * 1024 + ks * 2, en);
                        }
                    }
                }
                TCGEN05_COMMIT(sb + SM_DONE + sh * 8);
                TCGEN05_COMMIT(sb + SM_DONE + slx * 8);
            }
        }
    }

    {
        const int jlast = NSLOT - 1;
        mbar_wait(sb + SM_DONE + (jlast % 3) * 8, (uint32_t)((jlast / 3) & 1));
    }
    TCGEN05_FENCE_AFTER();
    __syncthreads();

    if (wid < 8) {
        const int tile = wid >> 2, sub = wid & 3;
        const int m = m0 + tile * 128 + sub * 32 + lane;
        float* pb = part + (((size_t)(tap * 4 + phase) * L1_MPAD + m) * COUT);
#pragma unroll
        for (int q = 0; q < 8; ++q) {
            const int c0 = q * 32;
            uint32_t regs[32];
            TCGEN05_LD_X32(regs, tmem + tile * 256 + c0);
            TCGEN05_WAIT_LD();
#pragma unroll
            for (int k4 = 0; k4 < 8; ++k4) {
                float4 v;
                v.x = __uint_as_float(regs[k4 * 4 + 0]);
                v.y = __uint_as_float(regs[k4 * 4 + 1]);
                v.z = __uint_as_float(regs[k4 * 4 + 2]);
                v.w = __uint_as_float(regs[k4 * 4 + 3]);
                *(float4*)(pb + c0 + k4 * 4) = v;
            }
        }
    }

    __syncthreads();
    if (tid < 3) MBARRIER_INVAL(sb + SM_FULL + tid * 8);
    else if (tid >= 32 && tid < 35) MBARRIER_INVAL(sb + SM_DONE + (tid - 32) * 8);
    __syncthreads();
    if (wid == 0) TCGEN05_DEALLOC(tmem, 512);
#else
    const int tid = threadIdx.x;
    const int phase = blockIdx.y;
    const int py = phase >> 1, px = phase & 1;
    const int tap = blockIdx.z;
    const int a = tap >> 1, bt = tap & 1;
    const int kh = 2 * a + 1 - py, kw = 2 * bt + 1 - px;
    const int m0 = blockIdx.x * 256;
    for (int idx = tid; idx < 256 * 256; idx += NTHR) {
        const int ml = idx >> 8, n = idx & 255;
        const int m = m0 + ml;
        if (m >= M) continue;
        const int bb = m / HWp; const int rem = m - bb * HWp;
        const int ty = rem / Wp; const int tx = rem - ty * Wp;
        const bf16* ah = Ah + ((size_t)(bb * H + ty + a) * W + tx + bt) * Cin;
        const bf16* al = Al + ((size_t)(bb * H + ty + a) * W + tx + bt) * Cin;
        const bf16* wh = Wh + ((size_t)((kh * 4 + kw) * COUT + n)) * Cin;
        const bf16* wl = Wl + ((size_t)((kh * 4 + kw) * COUT + n)) * Cin;
        float acc = 0.f;
        for (int c = 0; c < Cin; ++c) {
            const float av = __bfloat162float(ah[c]) + __bfloat162float(al[c]);
            const float wv = __bfloat162float(wh[c]) + __bfloat162float(wl[c]);
            acc = fmaf(av, wv, acc);
        }
        part[(((size_t)(tap * 4 + phase) * L1_MPAD + m) * COUT) + n] = acc;
    }
#endif
}

// Reduce L1 partials: sum 4 taps, BN + ReLU, bf16 hi/lo split, scatter NHWC.
__global__ __launch_bounds__(256)
void reduce_l1(const float* __restrict__ part,
               const float* __restrict__ gma, const float* __restrict__ bta,
               const float* __restrict__ mu,  const float* __restrict__ var,
               bf16* __restrict__ Yh, bf16* __restrict__ Yl)
{
    const int t = blockIdx.x * 256 + threadIdx.x;
    if (t >= 4 * L1_M * 64) return;
    const int n4 = t & 63;
    const int rest = t >> 6;
    const int m = rest % L1_M;
    const int phase = rest / L1_M;
    const int py = phase >> 1, px = phase & 1;

    float4 acc = make_float4(0.f, 0.f, 0.f, 0.f);
#pragma unroll
    for (int tap = 0; tap < 4; ++tap) {
        const float4 v = *(const float4*)(part + ((size_t)(tap * 4 + phase) * L1_MPAD + m) * COUT + n4 * 4);
        acc.x += v.x; acc.y += v.y; acc.z += v.z; acc.w += v.w;
    }
    const int c = n4 * 4;
    float vv[4] = {acc.x, acc.y, acc.z, acc.w};
    bf16 hb[4], lb[4];
#pragma unroll
    for (int e = 0; e < 4; ++e) {
        const float s = gma[c + e] * rsqrtf(var[c + e] + BN_EPS);
        const float bi = bta[c + e] - mu[c + e] * s;
        const float v = fmaxf(fmaf(vv[e], s, bi), 0.f);
        split_bf(v, hb[e], lb[e]);
    }
    const int bb = m / 35; const int rem = m - bb * 35;
    const int ty = rem / 5; const int tx = rem - ty * 5;
    const int oy = 2 * ty + py, ox = 2 * tx + px;
    const size_t o = ((size_t)(bb * 14 + oy) * 10 + ox) * COUT + c;
    *(__nv_bfloat162*)(Yh + o)     = __nv_bfloat162(hb[0], hb[1]);
    *(__nv_bfloat162*)(Yh + o + 2) = __nv_bfloat162(hb[2], hb[3]);
    *(__nv_bfloat162*)(Yl + o)     = __nv_bfloat162(lb[0], lb[1]);
    *(__nv_bfloat162*)(Yl + o + 2) = __nv_bfloat162(lb[2], lb[3]);
}

// ===========================================================================
// Kernel B: m-paired 256x256 tiles for L2/L3 (Cin=256, K=1024, NK=16).
// mode 1: BN+ReLU bf16 hi/lo store (L2).
// mode 0: BN+ReLU + fused 1x1 conv (256->17)+bias -> transposed heatmap (L3).
// ===========================================================================
__global__ __launch_bounds__(NTHR, 1)
void deconv_tc2(const bf16* __restrict__ Ah, const bf16* __restrict__ Al,
                const bf16* __restrict__ Wh, const bf16* __restrict__ Wl,
                const float* __restrict__ gma, const float* __restrict__ bta,
                const float* __restrict__ mu,  const float* __restrict__ var,
                bf16* __restrict__ Yh, bf16* __restrict__ Yl,
                const float* __restrict__ wfp, const float* __restrict__ bfp,
                float* __restrict__ hmp,
                int H, int W, int Cin, int mode)
{
#if TCPATH
    extern __shared__ char smem[];
    const uint32_t sb = smem_u32(smem);
    const int tid = threadIdx.x;
    const int wid = tid >> 5, lane = tid & 31;

    const int phase = blockIdx.y;
    const int py = phase >> 1, px = phase & 1;
    const int m0 = blockIdx.x * 256;
    const int Hp = H - 1, Wp = W - 1;
    const int HWp = Hp * Wp;
    const int M = BDIM_B * HWp;
    const int NK = Cin >> 4;               // (4*Cin)/64
    const int NSLOT = 2 * NK;

    if (wid == 0) { TCGEN05_ALLOC(sb + SM_TMEMPTR, 512); TCGEN05_RELINQ(); }
    if (tid < 256) {
        const float s = gma[tid] * rsqrtf(var[tid] + BN_EPS);
        ((float*)(smem + SM_SC))[tid] = s;
        ((float*)(smem + SM_BI))[tid] = bta[tid] - mu[tid] * s;
    }
    if (mode == 0) {
        for (int i = tid; i < COUT * KPT; i += NTHR)
            ((float*)(smem + SM_WF))[i] = wfp[i];
    }
    if (tid < 3) MBARRIER_INIT(sb + SM_FULL + tid * 8, 256);
    else if (tid >= 32 && tid < 35) MBARRIER_INIT(sb + SM_DONE + (tid - 32) * 8, 1);
    __syncthreads();
    uint32_t tmem;
    asm volatile("ld.shared.b32 %0, [%1];" : "=r"(tmem) : "r"(sb + SM_TMEMPTR));

    if (wid < 8) {
        const int seg = tid & 7;
        const int ro  = tid >> 3;
        size_t arowv[8], brow_base[8];
        uint32_t swoA[8], swoB[8];
#pragma unroll
        for (int j = 0; j < 8; ++j) {
            const int r = ro + 32 * j;     // 0..255
            const int tile = r >> 7, rr = r & 127;
            int mrow = m0 + r; if (mrow >= M) mrow = M - 1;
            const int bbA = mrow / HWp; const int remA = mrow - bbA * HWp;
            const int tyA = remA / Wp;  const int txA = remA - tyA * Wp;
            arowv[j] = ((size_t)(bbA * H + tyA) * W + txA) * Cin + seg * 8;
            swoA[j] = (uint32_t)(tile * 16384) + SWZ((uint32_t)(rr * 128 + seg * 16));
            brow_base[j] = (size_t)r * Cin + seg * 8;
            swoB[j] = (uint32_t)(OFF2_B + tile * 16384) + SWZ((uint32_t)(rr * 128 + seg * 16));
        }

        for (int sl = 0; sl < NSLOT; ++sl) {
            const int s3 = sl % 3;
            if (sl >= 3) mbar_wait(sb + SM_DONE + s3 * 8, (uint32_t)(((sl / 3) - 1) & 1));
            const int chunk = sl >> 1, half = sl & 1;
            const int kt = chunk * 64;
            const int tap = kt / Cin;
            const int ci0 = kt - tap * Cin;
            const int a = tap >> 1, bt = tap & 1;
            const int kh = 2 * a + 1 - py, kw = 2 * bt + 1 - px;
            const size_t aoff = (size_t)(a * W + bt) * Cin + ci0;
            const size_t boff = (size_t)(kh * 4 + kw) * COUT * Cin + ci0;
            const bf16* Aarr = half ? Al : Ah;
            const bf16* Warr = half ? Wl : Wh;
            const uint32_t stgo = SL_STAGE0 + s3 * SLOT_BYTES;
#pragma unroll
            for (int j = 0; j < 8; ++j)
                *(uint4*)(smem + stgo + swoA[j]) = *(const uint4*)(Aarr + arowv[j] + aoff);
#pragma unroll
            for (int j = 0; j < 8; ++j)
                *(uint4*)(smem + stgo + swoB[j]) = *(const uint4*)(Warr + boff + brow_base[j]);
            FENCE_ASYNC_SHARED();
            MBARRIER_ARRIVE(sb + SM_FULL + s3 * 8);
        }
    } else {
        if (elect_one()) {
            for (int i = 0; i < NK; ++i) {
                const int jh = 2 * i, jl = 2 * i + 1;
                const int sh = jh % 3, slx = jl % 3;
                mbar_wait(sb + SM_FULL + sh * 8, (uint32_t)((jh / 3) & 1));
                mbar_wait(sb + SM_FULL + slx * 8, (uint32_t)((jl / 3) & 1));
                const uint32_t stg_h = sb + SL_STAGE0 + sh * SLOT_BYTES;
                const uint32_t stg_l = sb + SL_STAGE0 + slx * SLOT_BYTES;
                const uint64_t dAh0 = MAKE_DESC(stg_h);
                const uint64_t dAh1 = MAKE_DESC(stg_h + 16384);
                const uint64_t dAl0 = MAKE_DESC(stg_l);
                const uint64_t dAl1 = MAKE_DESC(stg_l + 16384);
                const uint64_t dBh  = MAKE_DESC(stg_h + OFF2_B);
                const uint64_t dBl  = MAKE_DESC(stg_l + OFF2_B);
#pragma unroll
                for (int ks = 0; ks < 4; ++ks) {
#pragma unroll
                    for (int pass = 0; pass < 3; ++pass) {
                        const uint64_t da0 = (pass == 2) ? dAl0 : dAh0;
                        const uint64_t da1 = (pass == 2) ? dAl1 : dAh1;
                        const uint64_t db  = (pass == 1) ? dBl  : dBh;
                        const uint32_t en = (i > 0 || ks > 0 || pass > 0) ? 1u : 0u;
#pragma unroll
                        for (int nh = 0; nh < 2; ++nh) {
                            mma_bf16_ss(tmem + 0   + nh * 128, da0 + ks * 2, db + nh * 1024 + ks * 2, en);
                            mma_bf16_ss(tmem + 256 + nh * 128, da1 + ks * 2, db + nh * 1024 + ks * 2, en);
                        }
                    }
                }
                TCGEN05_COMMIT(sb + SM_DONE + sh * 8);
                TCGEN05_COMMIT(sb + SM_DONE + slx * 8);
            }
        }
    }

    {
        const int jlast = NSLOT - 1;
        mbar_wait(sb + SM_DONE + (jlast % 3) * 8, (uint32_t)((jlast / 3) & 1));
    }
    TCGEN05_FENCE_AFTER();
    __syncthreads();

    if (wid < 8) {
        const float* scs = (const float*)(smem + SM_SC);
        const float* bis = (const float*)(smem + SM_BI);
        const float* wfs = (const float*)(smem + SM_WF);
        const int tile = wid >> 2, sub = wid & 3;
        const int m = m0 + tile * 128 + sub * 32 + lane;
        const bool valid = (m < M);
        int bb = 0, ty = 0, tx = 0;
        if (valid) { bb = m / HWp; const int rem = m - bb * HWp; ty = rem / Wp; tx = rem - ty * Wp; }
        const int H2 = 2 * H - 2, W2 = 2 * W - 2;
        const int oy = 2 * ty + py, ox = 2 * tx + px;

        float hacc[KPT];
        if (mode == 0) {
#pragma unroll
            for (int k = 0; k < KPT; ++k) hacc[k] = bfp[k];
        }
        const size_t obase = ((size_t)(bb * H2 + oy) * W2 + ox) * COUT;

#pragma unroll
        for (int q = 0; q < 8; ++q) {
            const int c0 = q * 32;
            uint32_t regs[32];
            TCGEN05_LD_X32(regs, tmem + tile * 256 + c0);
            TCGEN05_WAIT_LD();
            if (valid) {
                if (mode == 0) {
#pragma unroll
                    for (int e = 0; e < 32; ++e) {
                        const int c = c0 + e;
                        const float v = fmaxf(fmaf(__uint_as_float(regs[e]), scs[c], bis[c]), 0.f);
                        const float* wr = wfs + c * KPT;
#pragma unroll
                        for (int k = 0; k < KPT; ++k)
                            hacc[k] = fmaf(v, wr[k], hacc[k]);
                    }
                } else {
#pragma unroll
                    for (int k4 = 0; k4 < 8; ++k4) {
                        bf16 hb[4], lb[4];
#pragma unroll
                        for (int e = 0; e < 4; ++e) {
                            const int c = c0 + k4 * 4 + e;
                            const float v = fmaxf(fmaf(__uint_as_float(regs[k4 * 4 + e]), scs[c], bis[c]), 0.f);
                            split_bf(v, hb[e], lb[e]);
                        }
                        const size_t o = obase + c0 + k4 * 4;
                        *(__nv_bfloat162*)(Yh + o)     = __nv_bfloat162(hb[0], hb[1]);
                        *(__nv_bfloat162*)(Yh + o + 2) = __nv_bfloat162(hb[2], hb[3]);
                        *(__nv_bfloat162*)(Yl + o)     = __nv_bfloat162(lb[0], lb[1]);
                        *(__nv_bfloat162*)(Yl + o + 2) = __nv_bfloat162(lb[2], lb[3]);
                    }
                }
            }
        }
        if (mode == 0 && valid) {
            const int pp = oy * WD + ox;
            float* hb = hmp + (size_t)bb * KPT * HWD + pp;
#pragma unroll
            for (int k = 0; k < KPT; ++k)
                hb[(size_t)k * HWD] = hacc[k];
        }
    }

    __syncthreads();
    if (tid < 3) MBARRIER_INVAL(sb + SM_FULL + tid * 8);
    else if (tid >= 32 && tid < 35) MBARRIER_INVAL(sb + SM_DONE + (tid - 32) * 8);
    __syncthreads();
    if (wid == 0) TCGEN05_DEALLOC(tmem, 512);
#else
    // ------------------ fallback (non-accelerated pass) --------------------
    const int tid = threadIdx.x;
    const int phase = blockIdx.y;
    const int py = phase >> 1, px = phase & 1;
    const int m0 = blockIdx.x * 256;
    const int Hp = H - 1, Wp = W - 1;
    const int HWp = Hp * Wp;
    const int M = BDIM_B * HWp;
    const int H2 = 2 * H - 2, W2 = 2 * W - 2;

    if (mode == 1) {
        for (int idx = tid; idx < 256 * 256; idx += NTHR) {
            const int ml = idx >> 8, n = idx & 255;
            const int m = m0 + ml;
            if (m >= M) continue;
            const int bb = m / HWp; const int rem = m - bb * HWp;
            const int ty = rem / Wp; const int tx = rem - ty * Wp;
            float acc = 0.f;
            for (int tap = 0; tap < 4; ++tap) {
                const int a = tap >> 1, bt = tap & 1;
                const int kh = 2 * a + 1 - py, kw = 2 * bt + 1 - px;
                const bf16* ah = Ah + ((size_t)(bb * H + ty + a) * W + tx + bt) * Cin;
                const bf16* al = Al + ((size_t)(bb * H + ty + a) * W + tx + bt) * Cin;
                const bf16* wh = Wh + ((size_t)((kh * 4 + kw) * COUT + n)) * Cin;
                const bf16* wl = Wl + ((size_t)((kh * 4 + kw) * COUT + n)) * Cin;
                for (int c = 0; c < Cin; ++c) {
                    const float av = __bfloat162float(ah[c]) + __bfloat162float(al[c]);
                    const float wv = __bfloat162float(wh[c]) + __bfloat162float(wl[c]);
                    acc = fmaf(av, wv, acc);
                }
            }
            const float s = gma[n] * rsqrtf(var[n] + BN_EPS);
            float v = fmaxf(fmaf(acc - mu[n], s, bta[n]), 0.f);
            const int oy = 2 * ty + py, ox = 2 * tx + px;
            const size_t o = ((size_t)(bb * H2 + oy) * W2 + ox) * COUT + n;
            bf16 h, l; split_bf(v, h, l);
            Yh[o] = h; Yl[o] = l;
        }
    } else {
        for (int ml = tid; ml < 256; ml += NTHR) {
            const int m = m0 + ml;
            if (m >= M) continue;
            const int bb = m / HWp; const int rem = m - bb * HWp;
            const int ty = rem / Wp; const int tx = rem - ty * Wp;
            float hacc[KPT];
            for (int k = 0; k < KPT; ++k) hacc[k] = bfp[k];
            for (int n = 0; n < COUT; ++n) {
                float acc = 0.f;
                for (int tap = 0; tap < 4; ++tap) {
                    const int a = tap >> 1, bt = tap & 1;
                    const int kh = 2 * a + 1 - py, kw = 2 * bt + 1 - px;
                    const bf16* ah = Ah + ((size_t)(bb * H + ty + a) * W + tx + bt) * Cin;
                    const bf16* al = Al + ((size_t)(bb * H + ty + a) * W + tx + bt) * Cin;
                    const bf16* wh = Wh + ((size_t)((kh * 4 + kw) * COUT + n)) * Cin;
                    const bf16* wl = Wl + ((size_t)((kh * 4 + kw) * COUT + n)) * Cin;
                    for (int c = 0; c < Cin; ++c) {
                        const float av = __bfloat162float(ah[c]) + __bfloat162float(al[c]);
                        const float wv = __bfloat162float(wh[c]) + __bfloat162float(wl[c]);
                        acc = fmaf(av, wv, acc);
                    }
                }
                const float s = gma[n] * rsqrtf(var[n] + BN_EPS);
                const float v = fmaxf(fmaf(acc - mu[n], s, bta[n]), 0.f);
                for (int k = 0; k < KPT; ++k)
                    hacc[k] = fmaf(v, wfp[n * KPT + k], hacc[k]);
            }
            const int oy = 2 * ty + py, ox = 2 * tx + px;
            const int pp = oy * WD + ox;
            for (int k = 0; k < KPT; ++k)
                hmp[(size_t)(bb * KPT + k) * HWD + pp] = hacc[k];
        }
    }
#endif
}

// ---------------------------------------------------------------------------
// Per-(b,k) argmax + subpixel refinement.
// ---------------------------------------------------------------------------
__global__ void detect_kernel(const float* __restrict__ hm, float* __restrict__ out)
{
    const float* row = hm + (size_t)blockIdx.x * HWD;
    const int tid = threadIdx.x;

    float best = -3.402823466e+38f; int bidx = 0x7fffffff;
    for (int i = tid; i < HWD; i += 128) {
        const float v = row[i];
        if (v > best) { best = v; bidx = i; }
    }
    __shared__ float sv[128];
    __shared__ int   si[128];
    sv[tid] = best; si[tid] = bidx;
    __syncthreads();
    for (int s = 64; s > 0; s >>= 1) {
        if (tid < s) {
            const float v2 = sv[tid + s]; const int i2 = si[tid + s];
            if (v2 > sv[tid] || (v2 == sv[tid] && i2 < si[tid])) { sv[tid] = v2; si[tid] = i2; }
        }
        __syncthreads();
    }
    if (tid == 0) {
        const float score = sv[0];
        const int idx = si[0];
        const bool pos = score > 0.f;
        const int pxi = pos ? (idx % WD) : 0;
        const int pyi = pos ? (idx / WD) : 0;
        const bool inner = (pxi > 0) && (pxi < WD - 1) && (pyi > 0) && (pyi < HD - 1);
        float dx = 0.f, dy = 0.f;
        if (inner) {
            const int base = pyi * WD + pxi;
            const float d1 = row[base + 1]  - row[base - 1];
            const float d2 = row[base + WD] - row[base - WD];
            dx = (d1 > 0.f) ? 0.25f : ((d1 < 0.f) ? -0.25f : 0.f);
            dy = (d2 > 0.f) ? 0.25f : ((d2 < 0.f) ? -0.25f : 0.f);
        }
        float* o = out + (size_t)blockIdx.x * 3;
        o[0] = (float)pxi + dx;
        o[1] = (float)pyi + dy;
        o[2] = score;
    }
}

// ---------------------------------------------------------------------------
extern "C" void kernel_launch(void* const* d_in, const int* in_sizes, int n_in,
                              void* d_out, int out_size)
{
    const float* x  = (const float*)d_in[0];
    const float* w1 = (const float*)d_in[1];
    const float* g1 = (const float*)d_in[2];
    const float* b1 = (const float*)d_in[3];
    const float* m1 = (const float*)d_in[4];
    const float* v1 = (const float*)d_in[5];
    const float* w2 = (const float*)d_in[6];
    const float* g2 = (const float*)d_in[7];
    const float* b2 = (const float*)d_in[8];
    const float* m2 = (const float*)d_in[9];
    const float* v2 = (const float*)d_in[10];
    const float* w3 = (const float*)d_in[11];
    const float* g3 = (const float*)d_in[12];
    const float* b3 = (const float*)d_in[13];
    const float* m3 = (const float*)d_in[14];
    const float* v3 = (const float*)d_in[15];
    const float* wf = (const float*)d_in[16];
    const float* bf = (const float*)d_in[17];
    float* out = (float*)d_out;

    bf16 *xh, *xl, *w1h, *w1l, *w2h, *w2l, *w3h, *w3l, *y1h, *y1l, *y2h, *y2l;
    float *p1, *hm;
    cudaGetSymbolAddress((void**)&xh,  g_xh);
    cudaGetSymbolAddress((void**)&xl,  g_xl);
    cudaGetSymbolAddress((void**)&w1h, g_w1h);
    cudaGetSymbolAddress((void**)&w1l, g_w1l);
    cudaGetSymbolAddress((void**)&w2h, g_w2h);
    cudaGetSymbolAddress((void**)&w2l, g_w2l);
    cudaGetSymbolAddress((void**)&w3h, g_w3h);
    cudaGetSymbolAddress((void**)&w3l, g_w3l);
    cudaGetSymbolAddress((void**)&p1,  g_p1);
    cudaGetSymbolAddress((void**)&y1h, g_y1h);
    cudaGetSymbolAddress((void**)&y1l, g_y1l);
    cudaGetSymbolAddress((void**)&y2h, g_y2h);
    cudaGetSymbolAddress((void**)&y2l, g_y2l);
    cudaGetSymbolAddress((void**)&hm,  g_hm);

    static bool attr_done = false;
    if (!attr_done) {
        cudaFuncSetAttribute(deconv_tc1s, cudaFuncAttributeMaxDynamicSharedMemorySize, SMEM2_TOTAL);
        cudaFuncSetAttribute(deconv_tc2,  cudaFuncAttributeMaxDynamicSharedMemorySize, SMEM2_TOTAL);
        attr_done = true;
    }

    // preprocess + L1 (tc1s kept in the profiled launch slot)
    split_kernel<<<4096, 256>>>(x, xh, xl, BDIM_B * 8 * 6 * 2048);
    wtrans_kernel<<<dim3(2048 / 32, COUT / 32, 16), dim3(32, 8)>>>(w1, w1h, w1l, 2048);
    wtrans_kernel<<<dim3(256 / 32,  COUT / 32, 16), dim3(32, 8)>>>(w2, w2h, w2l, 256);
    deconv_tc1s<<<dim3(9, 4, 4), NTHR, SMEM2_TOTAL>>>(xh, xl, w1h, w1l, p1);
    wtrans_kernel<<<dim3(256 / 32,  COUT / 32, 16), dim3(32, 8)>>>(w3, w3h, w3l, 256);
    reduce_l1<<<(4 * L1_M * 64 + 255) / 256, 256>>>(p1, g1, b1, m1, v1, y1h, y1l);

    // L2: M_phase = 7488 -> 30 m-pair tiles
    deconv_tc2<<<dim3(30, 4), NTHR, SMEM2_TOTAL>>>(y1h, y1l, w2h, w2l, g2, b2, m2, v2,
                                                   y2h, y2l, nullptr, nullptr, nullptr,
                                                   14, 10, 256, 1);
    // L3 + fused heatmap: M_phase = 27200 -> 107 m-pair tiles
    deconv_tc2<<<dim3(107, 4), NTHR, SMEM2_TOTAL>>>(y2h, y2l, w3h, w3l, g3, b3, m3, v3,
                                                    nullptr, nullptr, wf, bf, hm,
                                                    26, 18, 256, 0);
    // argmax + subpixel per (b, keypoint)
    detect_kernel<<<BDIM_B * KPT, 128>>>(hm, out);
}

// round 16
// speedup vs baseline: 2.1619x; 1.0532x over previous
#include <cuda_runtime.h>
#include <cuda_bf16.h>
#include <cstdint>

// ---------------------------------------------------------------------------
// SimplePose via tcgen05 bf16 hi/lo 3-pass GEMMs (fp32-near precision).
//   3x (conv_transpose k4 s2 pads(1,1) + BN + ReLU) -> 1x1 conv -> argmax det
// Phase decomposition (py,px): kh = 2a+1-py, iy = ty+a  -> dense GEMM
//   M = B*(H-1)*(W-1), K = 4*Cin, N = 256 per phase.
// Emulation: v = hi + lo with hi = bf16(v), lo = bf16(v - hi).
//   C = Ah*Bh + Ah*Bl + Al*Bh  (3 bf16 tcgen05 passes, fp32 TMEM accum)
//
// Round 16: latency hiding on top of the round-15 coalesced SS kernel:
//  (1) loader register pipeline: next slot's LDGs issued right after arrive,
//      overlapping the lag-3 done-wait (no wait->LDG serial chain);
//  (2) MMA issues pass-0 (Ah*Bh) right after the hi slot lands, waits for the
//      lo slot only before the cross passes;
//  (3) N=256 B descriptors halve dispatch count (24/chunk, same floor).
// ---------------------------------------------------------------------------

#if defined(__CUDA_ARCH_FEAT_SM103_ALL) || defined(__CUDA_ARCH_FEAT_SM100_ALL)
#define TCPATH 1
#else
#define TCPATH 0
#endif

#define BDIM_B   64
#define COUT     256
#define KPT      17
#define BN_EPS   1e-5f
#define HD 50
#define WD 34
#define HWD (HD * WD)          // 1700
#define NTHR 288               // 8 loader warps + 1 MMA warp

#define L1_MPAD 2304
#define L1_M 2240              // 64 * 7 * 5

typedef __nv_bfloat16 bf16;

// ---------------- scratch (static; cudaMalloc forbidden) -------------------
__device__ bf16  g_xh[BDIM_B * 8 * 6 * 2048];
__device__ bf16  g_xl[BDIM_B * 8 * 6 * 2048];
__device__ bf16  g_w1h[16 * COUT * 2048];
__device__ bf16  g_w1l[16 * COUT * 2048];
__device__ bf16  g_w2h[16 * COUT * 256];
__device__ bf16  g_w2l[16 * COUT * 256];
__device__ bf16  g_w3h[16 * COUT * 256];
__device__ bf16  g_w3l[16 * COUT * 256];
__device__ float g_p1 [4 * 4 * L1_MPAD * COUT];
__device__ bf16  g_y1h[BDIM_B * 14 * 10 * COUT];
__device__ bf16  g_y1l[BDIM_B * 14 * 10 * COUT];
__device__ bf16  g_y2h[BDIM_B * 26 * 18 * COUT];
__device__ bf16  g_y2l[BDIM_B * 26 * 18 * COUT];
__device__ float g_hm [BDIM_B * KPT * HWD];

// ---------------------------- helpers --------------------------------------
__device__ __forceinline__ void split_bf(float v, bf16& h, bf16& l) {
    h = __float2bfloat16_rn(v);
    l = __float2bfloat16_rn(v - __bfloat162float(h));
}

#if TCPATH
__device__ __forceinline__ uint32_t smem_u32(const void* p) {
    uint32_t a;
    asm("{ .reg .u64 t; cvta.to.shared.u64 t, %1; cvt.u32.u64 %0, t; }" : "=r"(a) : "l"(p));
    return a;
}
__device__ __forceinline__ uint32_t elect_one() {
    uint32_t pr;
    asm volatile("{\n\t.reg .pred p;\n\telect.sync _|p, 0xFFFFFFFF;\n\tselp.b32 %0, 1, 0, p;\n\t}" : "=r"(pr));
    return pr;
}

#define MBARRIER_INIT(addr, cnt) \
    asm volatile("mbarrier.init.shared.b64 [%0], %1;" :: "r"(addr), "r"(cnt) : "memory")
#define MBARRIER_INVAL(addr) \
    asm volatile("mbarrier.inval.shared.b64 [%0];" :: "r"(addr) : "memory")
#define MBARRIER_ARRIVE(addr) \
    asm volatile("mbarrier.arrive.release.cta.shared::cta.b64 _, [%0];" :: "r"(addr) : "memory")
__device__ __forceinline__ void mbar_wait(uint32_t mbar, uint32_t parity) {
    asm volatile(
        "{\n\t.reg .pred P;\n\t"
        "WL%=:\n\t"
        "mbarrier.try_wait.parity.acquire.cta.shared::cta.b64 P, [%0], %1, 0x989680;\n\t"
        "@P bra.uni WD%=;\n\t"
        "bra.uni WL%=;\n\t"
        "WD%=:\n\t}"
        :: "r"(mbar), "r"(parity) : "memory");
}
#define TCGEN05_ALLOC(sm, n) \
    asm volatile("tcgen05.alloc.cta_group::1.sync.aligned.shared::cta.b32 [%0], %1;" :: "r"(sm), "r"(n) : "memory")
#define TCGEN05_DEALLOC(tm, n) \
    asm volatile("tcgen05.dealloc.cta_group::1.sync.aligned.b32 %0, %1;" :: "r"(tm), "r"(n))
#define TCGEN05_RELINQ() \
    asm volatile("tcgen05.relinquish_alloc_permit.cta_group::1.sync.aligned;")
#define TCGEN05_COMMIT(mb) \
    asm volatile("tcgen05.commit.cta_group::1.mbarrier::arrive::one.shared::cluster.b64 [%0];" :: "r"(mb) : "memory")
#define TCGEN05_FENCE_AFTER() \
    asm volatile("tcgen05.fence::after_thread_sync;" ::: "memory")
#define TCGEN05_WAIT_LD() \
    asm volatile("tcgen05.wait::ld.sync.aligned;" ::: "memory")
#define FENCE_ASYNC_SHARED() \
    asm volatile("fence.proxy.async.shared::cta;" ::: "memory")

#define TCGEN05_LD_X32(r, tm) \
    asm volatile( \
        "tcgen05.ld.sync.aligned.32x32b.x32.b32 " \
        "{%0, %1, %2, %3, %4, %5, %6, %7, " \
        " %8, %9, %10, %11, %12, %13, %14, %15, " \
        " %16, %17, %18, %19, %20, %21, %22, %23, " \
        " %24, %25, %26, %27, %28, %29, %30, %31}, [%32];" \
        : "=r"((r)[0]),  "=r"((r)[1]),  "=r"((r)[2]),  "=r"((r)[3]), \
          "=r"((r)[4]),  "=r"((r)[5]),  "=r"((r)[6]),  "=r"((r)[7]), \
          "=r"((r)[8]),  "=r"((r)[9]),  "=r"((r)[10]), "=r"((r)[11]), \
          "=r"((r)[12]), "=r"((r)[13]), "=r"((r)[14]), "=r"((r)[15]), \
          "=r"((r)[16]), "=r"((r)[17]), "=r"((r)[18]), "=r"((r)[19]), \
          "=r"((r)[20]), "=r"((r)[21]), "=r"((r)[22]), "=r"((r)[23]), \
          "=r"((r)[24]), "=r"((r)[25]), "=r"((r)[26]), "=r"((r)[27]), \
          "=r"((r)[28]), "=r"((r)[29]), "=r"((r)[30]), "=r"((r)[31]) \
        : "r"(tm))

// SMEM descriptor (K-major SW128: LBO=1, SBO=64, version=1, layout=2)
#define SMEM_DESC_BASE \
    ((uint64_t(2) << 61) | (uint64_t(1) << 46) | (uint64_t(64) << 32) | (uint64_t(1) << 16))
#define MAKE_DESC(addr) (SMEM_DESC_BASE | ((uint64_t)((addr) >> 4) & 0x3FFF))

// bf16 MMA, cta_group::1, M=128, N=256, K=16 per issue (SS)
#define IDESC_BF16_N256 ((1u << 4) | (1u << 7) | (1u << 10) | (32u << 17) | (8u << 24))

__device__ __forceinline__ void mma_bf16_ss(uint32_t d, uint64_t da, uint64_t db,
                                            uint32_t en) {
    asm volatile(
        "{\n\t.reg .pred p;\n\t"
        "setp.ne.u32 p, %4, 0;\n\t"
        "tcgen05.mma.cta_group::1.kind::f16 [%0], %1, %2, %3, {%5, %5, %5, %5}, p;\n\t"
        "}"
        :: "r"(d), "l"(da), "l"(db), "r"(IDESC_BF16_N256), "r"(en), "r"(0u)
        : "memory");
}
#endif  // TCPATH

#define SWZ(o) ((o) ^ (((o) >> 3) & 0x70))

// SMEM layout: slot = one (chunk K=64, hi-or-lo half): A 2x128 rows x 128B,
// B 256 rows x 128B (contiguous -> single N=256 descriptor). Ring of 3.
#define SLOT_BYTES 65536
#define OFF2_B 32768
#define SM_TMEMPTR 0
#define SM_FULL 8
#define SM_DONE 32
#define SM_SC 64
#define SM_BI (64 + 1024)
#define SL_STAGE0 4096
#define SM_WF (SL_STAGE0 + 3 * SLOT_BYTES)          // 200704: wf[256*17]
#define SMEM2_TOTAL (SM_WF + COUT * KPT * 4)         // 218112

// ---------------------------------------------------------------------------
// Preprocess
// ---------------------------------------------------------------------------
__global__ void split_kernel(const float* __restrict__ in, bf16* __restrict__ hi,
                             bf16* __restrict__ lo, int n)
{
    for (int i = blockIdx.x * blockDim.x + threadIdx.x; i < n; i += gridDim.x * blockDim.x) {
        bf16 h, l; split_bf(in[i], h, l);
        hi[i] = h; lo[i] = l;
    }
}

__global__ void wtrans_kernel(const float* __restrict__ w, bf16* __restrict__ th,
                              bf16* __restrict__ tl, int Cin)
{
    __shared__ float tile[32][33];
    const int t = blockIdx.z;
    const int ci0 = blockIdx.x * 32, co0 = blockIdx.y * 32;
    const int tx = threadIdx.x, ty = threadIdx.y;
#pragma unroll
    for (int i = 0; i < 4; ++i)
        tile[ty + 8 * i][tx] = w[((size_t)(t * Cin + ci0 + ty + 8 * i)) * COUT + co0 + tx];
    __syncthreads();
#pragma unroll
    for (int i = 0; i < 4; ++i) {
        bf16 h, l; split_bf(tile[tx][ty + 8 * i], h, l);
        const size_t o = ((size_t)(t * COUT + co0 + ty + 8 * i)) * Cin + ci0 + tx;
        th[o] = h; tl[o] = l;
    }
}

// ===========================================================================
// Kernel L1S: split-K-by-tap m-paired 256x256 GEMM for L1 (Cin=2048).
// NK = 32 chunks of K64, NSLOT = 64. Coalesced + register-pipelined loaders.
// ===========================================================================
__global__ __launch_bounds__(NTHR, 1)
void deconv_tc1s(const bf16* __restrict__ Ah, const bf16* __restrict__ Al,
                 const bf16* __restrict__ Wh, const bf16* __restrict__ Wl,
                 float* __restrict__ part)
{
    const int H = 8, W = 6, Cin = 2048;
    const int Hp = 7, Wp = 5, HWp = 35;
    const int M = L1_M;
#if TCPATH
    extern __shared__ char smem[];
    const uint32_t sb = smem_u32(smem);
    const int tid = threadIdx.x;
    const int wid = tid >> 5, lane = tid & 31;

    const int phase = blockIdx.y;
    const int tap = blockIdx.z;
    const int a = tap >> 1, bt = tap & 1;
    const int py = phase >> 1, px = phase & 1;
    const int kh = 2 * a + 1 - py, kw = 2 * bt + 1 - px;
    const int m0 = blockIdx.x * 256;
    const int NK = Cin >> 6;               // 32 chunks of K=64
    const int NSLOT = 2 * NK;              // 64 slots

    if (wid == 0) { TCGEN05_ALLOC(sb + SM_TMEMPTR, 512); TCGEN05_RELINQ(); }
    if (tid < 3) MBARRIER_INIT(sb + SM_FULL + tid * 8, 256);
    else if (tid >= 32 && tid < 35) MBARRIER_INIT(sb + SM_DONE + (tid - 32) * 8, 1);
    __syncthreads();
    uint32_t tmem;
    asm volatile("ld.shared.b32 %0, [%1];" : "=r"(tmem) : "r"(sb + SM_TMEMPTR));

    if (wid < 8) {
        const int seg = tid & 7;           // 16B segment within 128B row
        const int ro  = tid >> 3;          // 0..31
        size_t arowv[8], browv[8];
        uint32_t swoA[8], swoB[8];
#pragma unroll
        for (int j = 0; j < 8; ++j) {
            const int r = ro + 32 * j;     // 0..255
            const int tile = r >> 7, rr = r & 127;
            int mrow = m0 + r; if (mrow >= M) mrow = M - 1;
            const int bbA = mrow / HWp; const int remA = mrow - bbA * HWp;
            const int tyA = remA / Wp;  const int txA = remA - tyA * Wp;
            arowv[j] = ((size_t)(bbA * H + tyA + a) * W + txA + bt) * Cin + seg * 8;
            swoA[j] = (uint32_t)(tile * 16384) + SWZ((uint32_t)(rr * 128 + seg * 16));
            browv[j] = ((size_t)((kh * 4 + kw) * COUT + r)) * Cin + seg * 8;
            swoB[j] = (uint32_t)(OFF2_B + tile * 16384) + SWZ((uint32_t)(rr * 128 + seg * 16));
        }

        uint4 bufA[8], bufB[8];
        // prefetch slot 0 (chunk 0, hi half)
#pragma unroll
        for (int j = 0; j < 8; ++j) bufA[j] = *(const uint4*)(Ah + arowv[j]);
#pragma unroll
        for (int j = 0; j < 8; ++j) bufB[j] = *(const uint4*)(Wh + browv[j]);

        for (int sl = 0; sl < NSLOT; ++sl) {
            const int s3 = sl % 3;
            if (sl >= 3) mbar_wait(sb + SM_DONE + s3 * 8, (uint32_t)(((sl / 3) - 1) & 1));
            const uint32_t stgo = SL_STAGE0 + s3 * SLOT_BYTES;
#pragma unroll
            for (int j = 0; j < 8; ++j) *(uint4*)(smem + stgo + swoA[j]) = bufA[j];
#pragma unroll
            for (int j = 0; j < 8; ++j) *(uint4*)(smem + stgo + swoB[j]) = bufB[j];
            FENCE_ASYNC_SHARED();
            MBARRIER_ARRIVE(sb + SM_FULL + s3 * 8);
            // issue next slot's LDGs now; latency overlaps the next done-wait
            if (sl + 1 < NSLOT) {
                const int ns = sl + 1;
                const int ci0 = (ns >> 1) * 64;
                const bf16* Aarr = (ns & 1) ? Al : Ah;
                const bf16* Warr = (ns & 1) ? Wl : Wh;
#pragma unroll
                for (int j = 0; j < 8; ++j) bufA[j] = *(const uint4*)(Aarr + arowv[j] + ci0);
#pragma unroll
                for (int j = 0; j < 8; ++j) bufB[j] = *(const uint4*)(Warr + browv[j] + ci0);
            }
        }
    } else {
        if (elect_one()) {
            for (int i = 0; i < NK; ++i) {
                const int jh = 2 * i, jl = 2 * i + 1;
                const int sh = jh % 3, slx = jl % 3;
                const uint32_t stg_h = sb + SL_STAGE0 + sh * SLOT_BYTES;
                const uint32_t stg_l = sb + SL_STAGE0 + slx * SLOT_BYTES;
                const uint64_t dAh0 = MAKE_DESC(stg_h);
                const uint64_t dAh1 = MAKE_DESC(stg_h + 16384);
                const uint64_t dAl0 = MAKE_DESC(stg_l);
                const uint64_t dAl1 = MAKE_DESC(stg_l + 16384);
                const uint64_t dBh  = MAKE_DESC(stg_h + OFF2_B);
                const uint64_t dBl  = MAKE_DESC(stg_l + OFF2_B);
                // pass 0 (Ah*Bh): only the hi slot is needed
                mbar_wait(sb + SM_FULL + sh * 8, (uint32_t)((jh / 3) & 1));
#pragma unroll
                for (int ks = 0; ks < 4; ++ks) {
                    const uint32_t en = (i > 0 || ks > 0) ? 1u : 0u;
                    mma_bf16_ss(tmem + 0,   dAh0 + ks * 2, dBh + ks * 2, en);
                    mma_bf16_ss(tmem + 256, dAh1 + ks * 2, dBh + ks * 2, en);
                }
                // cross passes need the lo slot
                mbar_wait(sb + SM_FULL + slx * 8, (uint32_t)((jl / 3) & 1));
#pragma unroll
                for (int ks = 0; ks < 4; ++ks) {
                    mma_bf16_ss(tmem + 0,   dAh0 + ks * 2, dBl + ks * 2, 1u);
                    mma_bf16_ss(tmem + 256, dAh1 + ks * 2, dBl + ks * 2, 1u);
                }
#pragma unroll
                for (int ks = 0; ks < 4; ++ks) {
                    mma_bf16_ss(tmem + 0,   dAl0 + ks * 2, dBh + ks * 2, 1u);
                    mma_bf16_ss(tmem + 256, dAl1 + ks * 2, dBh + ks * 2, 1u);
                }
                TCGEN05_COMMIT(sb + SM_DONE + sh * 8);
                TCGEN05_COMMIT(sb + SM_DONE + slx * 8);
            }
        }
    }

    {
        const int jlast = NSLOT - 1;
        mbar_wait(sb + SM_DONE + (jlast % 3) * 8, (uint32_t)((jlast / 3) & 1));
    }
    TCGEN05_FENCE_AFTER();
    __syncthreads();

    if (wid < 8) {
        const int tile = wid >> 2, sub = wid & 3;
        const int m = m0 + tile * 128 + sub * 32 + lane;
        float* pb = part + (((size_t)(tap * 4 + phase) * L1_MPAD + m) * COUT);
#pragma unroll
        for (int q = 0; q < 8; ++q) {
            const int c0 = q * 32;
            uint32_t regs[32];
            TCGEN05_LD_X32(regs, tmem + tile * 256 + c0);
            TCGEN05_WAIT_LD();
#pragma unroll
            for (int k4 = 0; k4 < 8; ++k4) {
                float4 v;
                v.x = __uint_as_float(regs[k4 * 4 + 0]);
                v.y = __uint_as_float(regs[k4 * 4 + 1]);
                v.z = __uint_as_float(regs[k4 * 4 + 2]);
                v.w = __uint_as_float(regs[k4 * 4 + 3]);
                *(float4*)(pb + c0 + k4 * 4) = v;
            }
        }
    }

    __syncthreads();
    if (tid < 3) MBARRIER_INVAL(sb + SM_FULL + tid * 8);
    else if (tid >= 32 && tid < 35) MBARRIER_INVAL(sb + SM_DONE + (tid - 32) * 8);
    __syncthreads();
    if (wid == 0) TCGEN05_DEALLOC(tmem, 512);
#else
    const int tid = threadIdx.x;
    const int phase = blockIdx.y;
    const int py = phase >> 1, px = phase & 1;
    const int tap = blockIdx.z;
    const int a = tap >> 1, bt = tap & 1;
    const int kh = 2 * a + 1 - py, kw = 2 * bt + 1 - px;
    const int m0 = blockIdx.x * 256;
    for (int idx = tid; idx < 256 * 256; idx += NTHR) {
        const int ml = idx >> 8, n = idx & 255;
        const int m = m0 + ml;
        if (m >= M) continue;
        const int bb = m / HWp; const int rem = m - bb * HWp;
        const int ty = rem / Wp; const int tx = rem - ty * Wp;
        const bf16* ah = Ah + ((size_t)(bb * H + ty + a) * W + tx + bt) * Cin;
        const bf16* al = Al + ((size_t)(bb * H + ty + a) * W + tx + bt) * Cin;
        const bf16* wh = Wh + ((size_t)((kh * 4 + kw) * COUT + n)) * Cin;
        const bf16* wl = Wl + ((size_t)((kh * 4 + kw) * COUT + n)) * Cin;
        float acc = 0.f;
        for (int c = 0; c < Cin; ++c) {
            const float av = __bfloat162float(ah[c]) + __bfloat162float(al[c]);
            const float wv = __bfloat162float(wh[c]) + __bfloat162float(wl[c]);
            acc = fmaf(av, wv, acc);
        }
        part[(((size_t)(tap * 4 + phase) * L1_MPAD + m) * COUT) + n] = acc;
    }
#endif
}

// Reduce L1 partials: sum 4 taps, BN + ReLU, bf16 hi/lo split, scatter NHWC.
__global__ __launch_bounds__(256)
void reduce_l1(const float* __restrict__ part,
               const float* __restrict__ gma, const float* __restrict__ bta,
               const float* __restrict__ mu,  const float* __restrict__ var,
               bf16* __restrict__ Yh, bf16* __restrict__ Yl)
{
    const int t = blockIdx.x * 256 + threadIdx.x;
    if (t >= 4 * L1_M * 64) return;
    const int n4 = t & 63;
    const int rest = t >> 6;
    const int m = rest % L1_M;
    const int phase = rest / L1_M;
    const int py = phase >> 1, px = phase & 1;

    float4 acc = make_float4(0.f, 0.f, 0.f, 0.f);
#pragma unroll
    for (int tap = 0; tap < 4; ++tap) {
        const float4 v = *(const float4*)(part + ((size_t)(tap * 4 + phase) * L1_MPAD + m) * COUT + n4 * 4);
        acc.x += v.x; acc.y += v.y; acc.z += v.z; acc.w += v.w;
    }
    const int c = n4 * 4;
    float vv[4] = {acc.x, acc.y, acc.z, acc.w};
    bf16 hb[4], lb[4];
#pragma unroll
    for (int e = 0; e < 4; ++e) {
        const float s = gma[c + e] * rsqrtf(var[c + e] + BN_EPS);
        const float bi = bta[c + e] - mu[c + e] * s;
        const float v = fmaxf(fmaf(vv[e], s, bi), 0.f);
        split_bf(v, hb[e], lb[e]);
    }
    const int bb = m / 35; const int rem = m - bb * 35;
    const int ty = rem / 5; const int tx = rem - ty * 5;
    const int oy = 2 * ty + py, ox = 2 * tx + px;
    const size_t o = ((size_t)(bb * 14 + oy) * 10 + ox) * COUT + c;
    *(__nv_bfloat162*)(Yh + o)     = __nv_bfloat162(hb[0], hb[1]);
    *(__nv_bfloat162*)(Yh + o + 2) = __nv_bfloat162(hb[2], hb[3]);
    *(__nv_bfloat162*)(Yl + o)     = __nv_bfloat162(lb[0], lb[1]);
    *(__nv_bfloat162*)(Yl + o + 2) = __nv_bfloat162(lb[2], lb[3]);
}

// ===========================================================================
// Kernel B: m-paired 256x256 tiles for L2/L3 (Cin=256, K=1024, NK=16).
// mode 1: BN+ReLU bf16 hi/lo store (L2).
// mode 0: BN+ReLU + fused 1x1 conv (256->17)+bias -> transposed heatmap (L3).
// ===========================================================================
__global__ __launch_bounds__(NTHR, 1)
void deconv_tc2(const bf16* __restrict__ Ah, const bf16* __restrict__ Al,
                const bf16* __restrict__ Wh, const bf16* __restrict__ Wl,
                const float* __restrict__ gma, const float* __restrict__ bta,
                const float* __restrict__ mu,  const float* __restrict__ var,
                bf16* __restrict__ Yh, bf16* __restrict__ Yl,
                const float* __restrict__ wfp, const float* __restrict__ bfp,
                float* __restrict__ hmp,
                int H, int W, int Cin, int mode)
{
#if TCPATH
    extern __shared__ char smem[];
    const uint32_t sb = smem_u32(smem);
    const int tid = threadIdx.x;
    const int wid = tid >> 5, lane = tid & 31;

    const int phase = blockIdx.y;
    const int py = phase >> 1, px = phase & 1;
    const int m0 = blockIdx.x * 256;
    const int Hp = H - 1, Wp = W - 1;
    const int HWp = Hp * Wp;
    const int M = BDIM_B * HWp;
    const int NK = Cin >> 4;               // (4*Cin)/64
    const int NSLOT = 2 * NK;

    if (wid == 0) { TCGEN05_ALLOC(sb + SM_TMEMPTR, 512); TCGEN05_RELINQ(); }
    if (tid < 256) {
        const float s = gma[tid] * rsqrtf(var[tid] + BN_EPS);
        ((float*)(smem + SM_SC))[tid] = s;
        ((float*)(smem + SM_BI))[tid] = bta[tid] - mu[tid] * s;
    }
    if (mode == 0) {
        for (int i = tid; i < COUT * KPT; i += NTHR)
            ((float*)(smem + SM_WF))[i] = wfp[i];
    }
    if (tid < 3) MBARRIER_INIT(sb + SM_FULL + tid * 8, 256);
    else if (tid >= 32 && tid < 35) MBARRIER_INIT(sb + SM_DONE + (tid - 32) * 8, 1);
    __syncthreads();
    uint32_t tmem;
    asm volatile("ld.shared.b32 %0, [%1];" : "=r"(tmem) : "r"(sb + SM_TMEMPTR));

    if (wid < 8) {
        const int seg = tid & 7;
        const int ro  = tid >> 3;
        size_t arowv[8], brow_base[8];
        uint32_t swoA[8], swoB[8];
#pragma unroll
        for (int j = 0; j < 8; ++j) {
            const int r = ro + 32 * j;     // 0..255
            const int tile = r >> 7, rr = r & 127;
            int mrow = m0 + r; if (mrow >= M) mrow = M - 1;
            const int bbA = mrow / HWp; const int remA = mrow - bbA * HWp;
            const int tyA = remA / Wp;  const int txA = remA - tyA * Wp;
            arowv[j] = ((size_t)(bbA * H + tyA) * W + txA) * Cin + seg * 8;
            swoA[j] = (uint32_t)(tile * 16384) + SWZ((uint32_t)(rr * 128 + seg * 16));
            brow_base[j] = (size_t)r * Cin + seg * 8;
            swoB[j] = (uint32_t)(OFF2_B + tile * 16384) + SWZ((uint32_t)(rr * 128 + seg * 16));
        }

        // slot offset helpers
        auto slot_offs = [&](int sl, size_t& aoff, size_t& boff, int& half) {
            half = sl & 1;
            const int kt = (sl >> 1) * 64;
            const int tap = kt / Cin;
            const int ci0 = kt - tap * Cin;
            const int a = tap >> 1, bt = tap & 1;
            const int kh = 2 * a + 1 - py, kw = 2 * bt + 1 - px;
            aoff = (size_t)(a * W + bt) * Cin + ci0;
            boff = (size_t)(kh * 4 + kw) * COUT * Cin + ci0;
        };

        uint4 bufA[8], bufB[8];
        {   // prefetch slot 0
            size_t aoff, boff; int half;
            slot_offs(0, aoff, boff, half);
            const bf16* Aarr = half ? Al : Ah;
            const bf16* Warr = half ? Wl : Wh;
#pragma unroll
            for (int j = 0; j < 8; ++j) bufA[j] = *(const uint4*)(Aarr + arowv[j] + aoff);
#pragma unroll
            for (int j = 0; j < 8; ++j) bufB[j] = *(const uint4*)(Warr + boff + brow_base[j]);
        }

        for (int sl = 0; sl < NSLOT; ++sl) {
            const int s3 = sl % 3;
            if (sl >= 3) mbar_wait(sb + SM_DONE + s3 * 8, (uint32_t)(((sl / 3) - 1) & 1));
            const uint32_t stgo = SL_STAGE0 + s3 * SLOT_BYTES;
#pragma unroll
            for (int j = 0; j < 8; ++j) *(uint4*)(smem + stgo + swoA[j]) = bufA[j];
#pragma unroll
            for (int j = 0; j < 8; ++j) *(uint4*)(smem + stgo + swoB[j]) = bufB[j];
            FENCE_ASYNC_SHARED();
            MBARRIER_ARRIVE(sb + SM_FULL + s3 * 8);
            if (sl + 1 < NSLOT) {
                size_t aoff, boff; int half;
                slot_offs(sl + 1, aoff, boff, half);
                const bf16* Aarr = half ? Al : Ah;
                const bf16* Warr = half ? Wl : Wh;
#pragma unroll
                for (int j = 0; j < 8; ++j) bufA[j] = *(const uint4*)(Aarr + arowv[j] + aoff);
#pragma unroll
                for (int j = 0; j < 8; ++j) bufB[j] = *(const uint4*)(Warr + boff + brow_base[j]);
            }
        }
    } else {
        if (elect_one()) {
            for (int i = 0; i < NK; ++i) {
                const int jh = 2 * i, jl = 2 * i + 1;
                const int sh = jh % 3, slx = jl % 3;
                const uint32_t stg_h = sb + SL_STAGE0 + sh * SLOT_BYTES;
                const uint32_t stg_l = sb + SL_STAGE0 + slx * SLOT_BYTES;
                const uint64_t dAh0 = MAKE_DESC(stg_h);
                const uint64_t dAh1 = MAKE_DESC(stg_h + 16384);
                const uint64_t dAl0 = MAKE_DESC(stg_l);
                const uint64_t dAl1 = MAKE_DESC(stg_l + 16384);
                const uint64_t dBh  = MAKE_DESC(stg_h + OFF2_B);
                const uint64_t dBl  = MAKE_DESC(stg_l + OFF2_B);
                mbar_wait(sb + SM_FULL + sh * 8, (uint32_t)((jh / 3) & 1));
#pragma unroll
                for (int ks = 0; ks < 4; ++ks) {
                    const uint32_t en = (i > 0 || ks > 0) ? 1u : 0u;
                    mma_bf16_ss(tmem + 0,   dAh0 + ks * 2, dBh + ks * 2, en);
                    mma_bf16_ss(tmem + 256, dAh1 + ks * 2, dBh + ks * 2, en);
                }
                mbar_wait(sb + SM_FULL + slx * 8, (uint32_t)((jl / 3) & 1));
#pragma unroll
                for (int ks = 0; ks < 4; ++ks) {
                    mma_bf16_ss(tmem + 0,   dAh0 + ks * 2, dBl + ks * 2, 1u);
                    mma_bf16_ss(tmem + 256, dAh1 + ks * 2, dBl + ks * 2, 1u);
                }
#pragma unroll
                for (int ks = 0; ks < 4; ++ks) {
                    mma_bf16_ss(tmem + 0,   dAl0 + ks * 2, dBh + ks * 2, 1u);
                    mma_bf16_ss(tmem + 256, dAl1 + ks * 2, dBh + ks * 2, 1u);
                }
                TCGEN05_COMMIT(sb + SM_DONE + sh * 8);
                TCGEN05_COMMIT(sb + SM_DONE + slx * 8);
            }
        }
    }

    {
        const int jlast = NSLOT - 1;
        mbar_wait(sb + SM_DONE + (jlast % 3) * 8, (uint32_t)((jlast / 3) & 1));
    }
    TCGEN05_FENCE_AFTER();
    __syncthreads();

    if (wid < 8) {
        const float* scs = (const float*)(smem + SM_SC);
        const float* bis = (const float*)(smem + SM_BI);
        const float* wfs = (const float*)(smem + SM_WF);
        const int tile = wid >> 2, sub = wid & 3;
        const int m = m0 + tile * 128 + sub * 32 + lane;
        const bool valid = (m < M);
        int bb = 0, ty = 0, tx = 0;
        if (valid) { bb = m / HWp; const int rem = m - bb * HWp; ty = rem / Wp; tx = rem - ty * Wp; }
        const int H2 = 2 * H - 2, W2 = 2 * W - 2;
        const int oy = 2 * ty + py, ox = 2 * tx + px;

        float hacc[KPT];
        if (mode == 0) {
#pragma unroll
            for (int k = 0; k < KPT; ++k) hacc[k] = bfp[k];
        }
        const size_t obase = ((size_t)(bb * H2 + oy) * W2 + ox) * COUT;

#pragma unroll
        for (int q = 0; q < 8; ++q) {
            const int c0 = q * 32;
            uint32_t regs[32];
            TCGEN05_LD_X32(regs, tmem + tile * 256 + c0);
            TCGEN05_WAIT_LD();
            if (valid) {
                if (mode == 0) {
#pragma unroll
                    for (int e = 0; e < 32; ++e) {
                        const int c = c0 + e;
                        const float v = fmaxf(fmaf(__uint_as_float(regs[e]), scs[c], bis[c]), 0.f);
                        const float* wr = wfs + c * KPT;
#pragma unroll
                        for (int k = 0; k < KPT; ++k)
                            hacc[k] = fmaf(v, wr[k], hacc[k]);
                    }
                } else {
#pragma unroll
                    for (int k4 = 0; k4 < 8; ++k4) {
                        bf16 hb[4], lb[4];
#pragma unroll
                        for (int e = 0; e < 4; ++e) {
                            const int c = c0 + k4 * 4 + e;
                            const float v = fmaxf(fmaf(__uint_as_float(regs[k4 * 4 + e]), scs[c], bis[c]), 0.f);
                            split_bf(v, hb[e], lb[e]);
                        }
                        const size_t o = obase + c0 + k4 * 4;
                        *(__nv_bfloat162*)(Yh + o)     = __nv_bfloat162(hb[0], hb[1]);
                        *(__nv_bfloat162*)(Yh + o + 2) = __nv_bfloat162(hb[2], hb[3]);
                        *(__nv_bfloat162*)(Yl + o)     = __nv_bfloat162(lb[0], lb[1]);
                        *(__nv_bfloat162*)(Yl + o + 2) = __nv_bfloat162(lb[2], lb[3]);
                    }
                }
            }
        }
        if (mode == 0 && valid) {
            const int pp = oy * WD + ox;
            float* hb = hmp + (size_t)bb * KPT * HWD + pp;
#pragma unroll
            for (int k = 0; k < KPT; ++k)
                hb[(size_t)k * HWD] = hacc[k];
        }
    }

    __syncthreads();
    if (tid < 3) MBARRIER_INVAL(sb + SM_FULL + tid * 8);
    else if (tid >= 32 && tid < 35) MBARRIER_INVAL(sb + SM_DONE + (tid - 32) * 8);
    __syncthreads();
    if (wid == 0) TCGEN05_DEALLOC(tmem, 512);
#else
    // ------------------ fallback (non-accelerated pass) --------------------
    const int tid = threadIdx.x;
    const int phase = blockIdx.y;
    const int py = phase >> 1, px = phase & 1;
    const int m0 = blockIdx.x * 256;
    const int Hp = H - 1, Wp = W - 1;
    const int HWp = Hp * Wp;
    const int M = BDIM_B * HWp;
    const int H2 = 2 * H - 2, W2 = 2 * W - 2;

    if (mode == 1) {
        for (int idx = tid; idx < 256 * 256; idx += NTHR) {
            const int ml = idx >> 8, n = idx & 255;
            const int m = m0 + ml;
            if (m >= M) continue;
            const int bb = m / HWp; const int rem = m - bb * HWp;
            const int ty = rem / Wp; const int tx = rem - ty * Wp;
            float acc = 0.f;
            for (int tap = 0; tap < 4; ++tap) {
                const int a = tap >> 1, bt = tap & 1;
                const int kh = 2 * a + 1 - py, kw = 2 * bt + 1 - px;
                const bf16* ah = Ah + ((size_t)(bb * H + ty + a) * W + tx + bt) * Cin;
                const bf16* al = Al + ((size_t)(bb * H + ty + a) * W + tx + bt) * Cin;
                const bf16* wh = Wh + ((size_t)((kh * 4 + kw) * COUT + n)) * Cin;
                const bf16* wl = Wl + ((size_t)((kh * 4 + kw) * COUT + n)) * Cin;
                for (int c = 0; c < Cin; ++c) {
                    const float av = __bfloat162float(ah[c]) + __bfloat162float(al[c]);
                    const float wv = __bfloat162float(wh[c]) + __bfloat162float(wl[c]);
                    acc = fmaf(av, wv, acc);
                }
            }
            const float s = gma[n] * rsqrtf(var[n] + BN_EPS);
            float v = fmaxf(fmaf(acc - mu[n], s, bta[n]), 0.f);
            const int oy = 2 * ty + py, ox = 2 * tx + px;
            const size_t o = ((size_t)(bb * H2 + oy) * W2 + ox) * COUT + n;
            bf16 h, l; split_bf(v, h, l);
            Yh[o] = h; Yl[o] = l;
        }
    } else {
        for (int ml = tid; ml < 256; ml += NTHR) {
            const int m = m0 + ml;
            if (m >= M) continue;
            const int bb = m / HWp; const int rem = m - bb * HWp;
            const int ty = rem / Wp; const int tx = rem - ty * Wp;
            float hacc[KPT];
            for (int k = 0; k < KPT; ++k) hacc[k] = bfp[k];
            for (int n = 0; n < COUT; ++n) {
                float acc = 0.f;
                for (int tap = 0; tap < 4; ++tap) {
                    const int a = tap >> 1, bt = tap & 1;
                    const int kh = 2 * a + 1 - py, kw = 2 * bt + 1 - px;
                    const bf16* ah = Ah + ((size_t)(bb * H + ty + a) * W + tx + bt) * Cin;
                    const bf16* al = Al + ((size_t)(bb * H + ty + a) * W + tx + bt) * Cin;
                    const bf16* wh = Wh + ((size_t)((kh * 4 + kw) * COUT + n)) * Cin;
                    const bf16* wl = Wl + ((size_t)((kh * 4 + kw) * COUT + n)) * Cin;
                    for (int c = 0; c < Cin; ++c) {
                        const float av = __bfloat162float(ah[c]) + __bfloat162float(al[c]);
                        const float wv = __bfloat162float(wh[c]) + __bfloat162float(wl[c]);
                        acc = fmaf(av, wv, acc);
                    }
                }
                const float s = gma[n] * rsqrtf(var[n] + BN_EPS);
                const float v = fmaxf(fmaf(acc - mu[n], s, bta[n]), 0.f);
                for (int k = 0; k < KPT; ++k)
                    hacc[k] = fmaf(v, wfp[n * KPT + k], hacc[k]);
            }
            const int oy = 2 * ty + py, ox = 2 * tx + px;
            const int pp = oy * WD + ox;
            for (int k = 0; k < KPT; ++k)
                hmp[(size_t)(bb * KPT + k) * HWD + pp] = hacc[k];
        }
    }
#endif
}

// ---------------------------------------------------------------------------
// Per-(b,k) argmax + subpixel refinement.
// ---------------------------------------------------------------------------
__global__ void detect_kernel(const float* __restrict__ hm, float* __restrict__ out)
{
    const float* row = hm + (size_t)blockIdx.x * HWD;
    const int tid = threadIdx.x;

    float best = -3.402823466e+38f; int bidx = 0x7fffffff;
    for (int i = tid; i < HWD; i += 128) {
        const float v = row[i];
        if (v > best) { best = v; bidx = i; }
    }
    __shared__ float sv[128];
    __shared__ int   si[128];
    sv[tid] = best; si[tid] = bidx;
    __syncthreads();
    for (int s = 64; s > 0; s >>= 1) {
        if (tid < s) {
            const float v2 = sv[tid + s]; const int i2 = si[tid + s];
            if (v2 > sv[tid] || (v2 == sv[tid] && i2 < si[tid])) { sv[tid] = v2; si[tid] = i2; }
        }
        __syncthreads();
    }
    if (tid == 0) {
        const float score = sv[0];
        const int idx = si[0];
        const bool pos = score > 0.f;
        const int pxi = pos ? (idx % WD) : 0;
        const int pyi = pos ? (idx / WD) : 0;
        const bool inner = (pxi > 0) && (pxi < WD - 1) && (pyi > 0) && (pyi < HD - 1);
        float dx = 0.f, dy = 0.f;
        if (inner) {
            const int base = pyi * WD + pxi;
            const float d1 = row[base + 1]  - row[base - 1];
            const float d2 = row[base + WD] - row[base - WD];
            dx = (d1 > 0.f) ? 0.25f : ((d1 < 0.f) ? -0.25f : 0.f);
            dy = (d2 > 0.f) ? 0.25f : ((d2 < 0.f) ? -0.25f : 0.f);
        }
        float* o = out + (size_t)blockIdx.x * 3;
        o[0] = (float)pxi + dx;
        o[1] = (float)pyi + dy;
        o[2] = score;
    }
}

// ---------------------------------------------------------------------------
extern "C" void kernel_launch(void* const* d_in, const int* in_sizes, int n_in,
                              void* d_out, int out_size)
{
    const float* x  = (const float*)d_in[0];
    const float* w1 = (const float*)d_in[1];
    const float* g1 = (const float*)d_in[2];
    const float* b1 = (const float*)d_in[3];
    const float* m1 = (const float*)d_in[4];
    const float* v1 = (const float*)d_in[5];
    const float* w2 = (const float*)d_in[6];
    const float* g2 = (const float*)d_in[7];
    const float* b2 = (const float*)d_in[8];
    const float* m2 = (const float*)d_in[9];
    const float* v2 = (const float*)d_in[10];
    const float* w3 = (const float*)d_in[11];
    const float* g3 = (const float*)d_in[12];
    const float* b3 = (const float*)d_in[13];
    const float* m3 = (const float*)d_in[14];
    const float* v3 = (const float*)d_in[15];
    const float* wf = (const float*)d_in[16];
    const float* bf = (const float*)d_in[17];
    float* out = (float*)d_out;

    bf16 *xh, *xl, *w1h, *w1l, *w2h, *w2l, *w3h, *w3l, *y1h, *y1l, *y2h, *y2l;
    float *p1, *hm;
    cudaGetSymbolAddress((void**)&xh,  g_xh);
    cudaGetSymbolAddress((void**)&xl,  g_xl);
    cudaGetSymbolAddress((void**)&w1h, g_w1h);
    cudaGetSymbolAddress((void**)&w1l, g_w1l);
    cudaGetSymbolAddress((void**)&w2h, g_w2h);
    cudaGetSymbolAddress((void**)&w2l, g_w2l);
    cudaGetSymbolAddress((void**)&w3h, g_w3h);
    cudaGetSymbolAddress((void**)&w3l, g_w3l);
    cudaGetSymbolAddress((void**)&p1,  g_p1);
    cudaGetSymbolAddress((void**)&y1h, g_y1h);
    cudaGetSymbolAddress((void**)&y1l, g_y1l);
    cudaGetSymbolAddress((void**)&y2h, g_y2h);
    cudaGetSymbolAddress((void**)&y2l, g_y2l);
    cudaGetSymbolAddress((void**)&hm,  g_hm);

    static bool attr_done = false;
    if (!attr_done) {
        cudaFuncSetAttribute(deconv_tc1s, cudaFuncAttributeMaxDynamicSharedMemorySize, SMEM2_TOTAL);
        cudaFuncSetAttribute(deconv_tc2,  cudaFuncAttributeMaxDynamicSharedMemorySize, SMEM2_TOTAL);
        attr_done = true;
    }

    // preprocess + L1 (tc1s kept in the profiled launch slot)
    split_kernel<<<4096, 256>>>(x, xh, xl, BDIM_B * 8 * 6 * 2048);
    wtrans_kernel<<<dim3(2048 / 32, COUT / 32, 16), dim3(32, 8)>>>(w1, w1h, w1l, 2048);
    wtrans_kernel<<<dim3(256 / 32,  COUT / 32, 16), dim3(32, 8)>>>(w2, w2h, w2l, 256);
    deconv_tc1s<<<dim3(9, 4, 4), NTHR, SMEM2_TOTAL>>>(xh, xl, w1h, w1l, p1);
    wtrans_kernel<<<dim3(256 / 32,  COUT / 32, 16), dim3(32, 8)>>>(w3, w3h, w3l, 256);
    reduce_l1<<<(4 * L1_M * 64 + 255) / 256, 256>>>(p1, g1, b1, m1, v1, y1h, y1l);

    // L2: M_phase = 7488 -> 30 m-pair tiles
    deconv_tc2<<<dim3(30, 4), NTHR, SMEM2_TOTAL>>>(y1h, y1l, w2h, w2l, g2, b2, m2, v2,
                                                   y2h, y2l, nullptr, nullptr, nullptr,
                                                   14, 10, 256, 1);
    // L3 + fused heatmap: M_phase = 27200 -> 107 m-pair tiles
    deconv_tc2<<<dim3(107, 4), NTHR, SMEM2_TOTAL>>>(y2h, y2l, w3h, w3l, g3, b3, m3, v3,
                                                    nullptr, nullptr, wf, bf, hm,
                                                    26, 18, 256, 0);
    // argmax + subpixel per (b, keypoint)
    detect_kernel<<<BDIM_B * KPT, 128>>>(hm, out);
}